// round 1
// baseline (speedup 1.0000x reference)
#include <cuda_runtime.h>
#include <math.h>

#define BATCH 64
#define WLEN  160000
#define NFRM  313          // 1 + 160000/512
#define HOP   512
#define NFFT  2048
#define MHALF 1024         // complex FFT length
#define NMELS 128
#define NBINS 1025
#define NPTS  130          // mel breakpoints

// ---------------- device scratch (no allocations allowed) ----------------
__device__ float2 g_tw[MHALF];          // W_2048^k, k=0..1023 (e^{-2*pi*i*k/2048})
__device__ float  g_win[NFFT];          // Hann window
__device__ float  g_fpts[NPTS];         // mel filterbank breakpoints (Hz)
__device__ float  g_mel[BATCH * NFRM * NMELS];   // mel power, layout [b][t][m]

// ---------------- init: constants in double precision ----------------
__global__ void init_kernel() {
    int i = blockIdx.x * blockDim.x + threadIdx.x;
    if (i < MHALF) {
        double ang = -2.0 * M_PI * (double)i / (double)NFFT;
        g_tw[i] = make_float2((float)cos(ang), (float)sin(ang));
    }
    if (i < NFFT) {
        g_win[i] = (float)(0.5 - 0.5 * cos(2.0 * M_PI * (double)i / (double)NFFT));
    }
    if (i < NPTS) {
        double mlo = 2595.0 * log10(1.0 + 20.0 / 700.0);
        double mhi = 2595.0 * log10(1.0 + 16000.0 / 700.0);
        double m = mlo + (mhi - mlo) * (double)i / (double)(NPTS - 1);
        double f = 700.0 * (pow(10.0, m / 2595.0) - 1.0);
        g_fpts[i] = (float)f;
    }
}

// ---------------- fused frame+window+FFT+power+mel ----------------
// one block per (frame t, batch b); 256 threads
__global__ __launch_bounds__(256) void melspec_kernel(const float* __restrict__ wave) {
    __shared__ float2 z[MHALF];     // 8 KB
    __shared__ float2 tws[MHALF];   // 8 KB
    __shared__ float  pw[NBINS];    // 4.1 KB
    __shared__ float  fp[NPTS];     // 0.5 KB

    const int t   = blockIdx.x;
    const int b   = blockIdx.y;
    const int tid = threadIdx.x;
    const float* __restrict__ wb = wave + (size_t)b * WLEN;

    // stage twiddles + breakpoints into shared
    #pragma unroll
    for (int i = tid; i < MHALF; i += 256) tws[i] = g_tw[i];
    if (tid < NPTS) fp[tid] = g_fpts[tid];

    // load frame with reflect padding + window, pack 2 reals -> 1 complex,
    // store in bit-reversed order
    const int p0 = t * HOP - (NFFT / 2);
    #pragma unroll
    for (int n = tid; n < MHALF; n += 256) {
        int j0 = p0 + 2 * n;
        int j1 = j0 + 1;
        int r0 = (j0 < 0) ? -j0 : ((j0 >= WLEN) ? 2 * WLEN - 2 - j0 : j0);
        int r1 = (j1 < 0) ? -j1 : ((j1 >= WLEN) ? 2 * WLEN - 2 - j1 : j1);
        float x0 = wb[r0] * g_win[2 * n];
        float x1 = wb[r1] * g_win[2 * n + 1];
        int rev = __brev((unsigned)n) >> 22;   // 10-bit reversal
        z[rev] = make_float2(x0, x1);
    }
    __syncthreads();

    // radix-2 DIT, 10 stages, 512 butterflies/stage, 2 per thread
    #pragma unroll
    for (int s = 0; s < 10; s++) {
        const int half = 1 << s;
        #pragma unroll
        for (int q = 0; q < 2; q++) {
            int j   = tid + q * 256;
            int pos = j & (half - 1);
            int i0  = ((j >> s) << (s + 1)) + pos;
            int i1  = i0 + half;
            float2 w = tws[pos << (10 - s)];
            float2 a = z[i0];
            float2 c = z[i1];
            float tr = c.x * w.x - c.y * w.y;
            float ti = c.x * w.y + c.y * w.x;
            z[i0] = make_float2(a.x + tr, a.y + ti);
            z[i1] = make_float2(a.x - tr, a.y - ti);
        }
        __syncthreads();
    }

    // unpack real FFT -> power spectrum (1025 bins)
    for (int k = tid; k < NBINS; k += 256) {
        float v;
        if (k == 0) {
            float2 z0 = z[0];
            float x = z0.x + z0.y;
            v = x * x;
        } else if (k == MHALF) {
            float2 z0 = z[0];
            float x = z0.x - z0.y;
            v = x * x;
        } else {
            float2 a = z[k];
            float2 c = z[MHALF - k];
            float ex = 0.5f * (a.x + c.x);
            float ey = 0.5f * (a.y - c.y);
            float ox = 0.5f * (a.y + c.y);
            float oy = -0.5f * (a.x - c.x);
            float2 w = tws[k];
            float xr = ex + ox * w.x - oy * w.y;
            float xi = ey + ox * w.y + oy * w.x;
            v = xr * xr + xi * xi;
        }
        pw[k] = v;
    }
    __syncthreads();

    // sparse triangular mel projection: thread m handles mel bin m
    if (tid < NMELS) {
        const float f0 = fp[tid];
        const float f1 = fp[tid + 1];
        const float f2 = fp[tid + 2];
        const float inv_d0 = 1.0f / (f1 - f0);
        const float inv_d1 = 1.0f / (f2 - f1);
        const float df = 16000.0f / 1024.0f;    // Hz per bin
        int klo = max(0, (int)(f0 / df));
        int khi = min(1024, (int)(f2 / df) + 1);
        float acc = 0.0f;
        for (int k = klo; k <= khi; k++) {
            float freq = (float)k * df;
            float w = fminf((freq - f0) * inv_d0, (f2 - freq) * inv_d1);
            w = fmaxf(w, 0.0f);
            acc = fmaf(pw[k], w, acc);
        }
        g_mel[((size_t)b * NFRM + t) * NMELS + tid] = acc;
    }
}

// ---------------- PCEN: sequential scan over t, one thread per (b,m) ----------------
__global__ __launch_bounds__(128) void pcen_kernel(float* __restrict__ out) {
    const int b = blockIdx.x;
    const int m = threadIdx.x;
    const float S = 0.025f;
    const float ONE_MS = 0.975f;
    const float EPS = 1e-6f;
    const float ALPHA = 0.98f;
    const float DELTA = 2.0f;
    const float DELTA_R = 1.41421356237309515f;  // 2^0.5

    float mst = 0.0f;
    const float* __restrict__ src = g_mel + (size_t)b * NFRM * NMELS + m;
    float* __restrict__ dst = out + ((size_t)b * NMELS + m) * NFRM;

    for (int t = 0; t < NFRM; t++) {
        float x = src[(size_t)t * NMELS];
        mst = fmaf(ONE_MS, mst, S * x);
        float denom = powf(EPS + mst, ALPHA);
        float p = sqrtf(x / denom + DELTA) - DELTA_R;
        dst[t] = p;
    }
}

extern "C" void kernel_launch(void* const* d_in, const int* in_sizes, int n_in,
                              void* d_out, int out_size) {
    const float* wave = (const float*)d_in[0];
    float* out = (float*)d_out;

    init_kernel<<<8, 256>>>();            // deterministic constant fill (cheap)
    dim3 grid(NFRM, BATCH);
    melspec_kernel<<<grid, 256>>>(wave);
    pcen_kernel<<<BATCH, NMELS>>>(out);
}

// round 2
// speedup vs baseline: 1.7229x; 1.7229x over previous
#include <cuda_runtime.h>
#include <math.h>

#define BATCH 64
#define WLEN  160000
#define NFRM  313          // 1 + 160000/512
#define HOP   512
#define NFFT  2048
#define MHALF 1024         // complex FFT length
#define NMELS 128
#define NPTS  130          // mel breakpoints

#define SK(i) ((i) + ((i) >> 3))     // bank-conflict skew
#define ZLEN  (1024 + 128)           // skewed array length

__device__ float g_mel[BATCH * NFRM * NMELS];   // mel power, layout [b][t][m]

__device__ __forceinline__ float2 cmul(float2 a, float2 b) {
    return make_float2(a.x * b.x - a.y * b.y, a.x * b.y + a.y * b.x);
}

// ---------------- fused frame+window+FFT+power+mel ----------------
// one block per (frame t, batch b); 256 threads; radix-4 DIT 1024-pt complex FFT
__global__ __launch_bounds__(256) void melspec_kernel(const float* __restrict__ wave) {
    __shared__ float  sr[ZLEN];      // staging re -> reused as power spectrum
    __shared__ float  si[ZLEN];      // staging im -> reused as mel breakpoints
    __shared__ float  zr[ZLEN];
    __shared__ float  zi[ZLEN];
    __shared__ float2 tws[MHALF];    // W_2048^k

    const int t   = blockIdx.x;
    const int b   = blockIdx.y;
    const int tid = threadIdx.x;
    const float* __restrict__ wb = wave + (size_t)b * WLEN;

    // ---- build twiddle table (4 __sincosf per thread) ----
    const float ANG = -(float)M_PI / 1024.0f;   // -2*pi/2048
    #pragma unroll
    for (int i = tid; i < MHALF; i += 256) {
        float s, c;
        __sincosf(ANG * (float)i, &s, &c);
        tws[i] = make_float2(c, s);
    }

    // ---- load frame (reflect pad) * Hann, pack 2 reals -> complex, natural order ----
    const int p0 = t * HOP - (NFFT / 2);
    const float CW = (float)M_PI / 1024.0f;     // window angle per sample
    if (p0 >= 0 && p0 + NFFT <= WLEN) {
        const float2* __restrict__ wv = (const float2*)(wb + p0);
        #pragma unroll
        for (int n = tid; n < MHALF; n += 256) {
            float2 v = wv[n];
            float a0 = CW * (float)(2 * n);
            float w0 = 0.5f - 0.5f * __cosf(a0);
            float w1 = 0.5f - 0.5f * __cosf(a0 + CW);
            sr[SK(n)] = v.x * w0;
            si[SK(n)] = v.y * w1;
        }
    } else {
        #pragma unroll
        for (int n = tid; n < NFFT; n += 256) {
            int j = p0 + n;
            int r = (j < 0) ? -j : ((j >= WLEN) ? 2 * WLEN - 2 - j : j);
            float w = 0.5f - 0.5f * __cosf(CW * (float)n);
            float v = wb[r] * w;
            if (n & 1) si[SK(n >> 1)] = v;
            else       sr[SK(n >> 1)] = v;
        }
    }
    __syncthreads();

    // ---- stage 0 (fused with digit-reversed gather; twiddle-free) ----
    {
        unsigned rj = __brev((unsigned)tid) >> 24;              // 8-bit reverse of tid
        rj = ((rj & 0x55u) << 1) | ((rj >> 1) & 0x55u);         // base-4 digit reverse
        float ar[4], ai[4];
        #pragma unroll
        for (int q = 0; q < 4; q++) {
            int idx = (q << 8) + (int)rj;
            ar[q] = sr[SK(idx)];
            ai[q] = si[SK(idx)];
        }
        float t0r = ar[0] + ar[2], t0i = ai[0] + ai[2];
        float t1r = ar[0] - ar[2], t1i = ai[0] - ai[2];
        float t2r = ar[1] + ar[3], t2i = ai[1] + ai[3];
        float t3r = ai[1] - ai[3], t3i = -(ar[1] - ar[3]);      // -i*(a1-a3)
        int o = 4 * tid;
        zr[SK(o + 0)] = t0r + t2r;  zi[SK(o + 0)] = t0i + t2i;
        zr[SK(o + 1)] = t1r + t3r;  zi[SK(o + 1)] = t1i + t3i;
        zr[SK(o + 2)] = t0r - t2r;  zi[SK(o + 2)] = t0i - t2i;
        zr[SK(o + 3)] = t1r - t3r;  zi[SK(o + 3)] = t1i - t3i;
    }
    __syncthreads();

    // ---- mel breakpoints into si (dead after stage 0) ----
    if (tid < NPTS) {
        const float mlo = 2595.0f * log10f(1.0f + 20.0f / 700.0f);
        const float mhi = 2595.0f * log10(1.0f + 16000.0f / 700.0f);
        float m = mlo + (mhi - mlo) * (float)tid / (float)(NPTS - 1);
        si[tid] = 700.0f * (exp10f(m / 2595.0f) - 1.0f);
    }

    // ---- stages 1..4 (radix-4 DIT) ----
    #pragma unroll
    for (int s = 1; s < 5; s++) {
        const int quarter = 1 << (2 * s);
        const int pos = tid & (quarter - 1);
        const int i0  = ((tid >> (2 * s)) << (2 * s + 2)) + pos;
        float2 w1 = tws[pos << (9 - 2 * s)];
        float2 w2 = cmul(w1, w1);
        float2 w3 = cmul(w2, w1);

        float ar[4], ai[4];
        #pragma unroll
        for (int q = 0; q < 4; q++) {
            int idx = i0 + q * quarter;
            ar[q] = zr[SK(idx)];
            ai[q] = zi[SK(idx)];
        }
        // apply twiddles to a1,a2,a3
        float b1r = ar[1] * w1.x - ai[1] * w1.y, b1i = ar[1] * w1.y + ai[1] * w1.x;
        float b2r = ar[2] * w2.x - ai[2] * w2.y, b2i = ar[2] * w2.y + ai[2] * w2.x;
        float b3r = ar[3] * w3.x - ai[3] * w3.y, b3i = ar[3] * w3.y + ai[3] * w3.x;

        float t0r = ar[0] + b2r, t0i = ai[0] + b2i;
        float t1r = ar[0] - b2r, t1i = ai[0] - b2i;
        float t2r = b1r + b3r,   t2i = b1i + b3i;
        float t3r = b1i - b3i,   t3i = -(b1r - b3r);            // -i*(b1-b3)

        __syncthreads();   // protect against WAR within same array? loads above done; need all loads before stores
        zr[SK(i0)]               = t0r + t2r;  zi[SK(i0)]               = t0i + t2i;
        zr[SK(i0 + quarter)]     = t1r + t3r;  zi[SK(i0 + quarter)]     = t1i + t3i;
        zr[SK(i0 + 2 * quarter)] = t0r - t2r;  zi[SK(i0 + 2 * quarter)] = t0i - t2i;
        zr[SK(i0 + 3 * quarter)] = t1r - t3r;  zi[SK(i0 + 3 * quarter)] = t1i - t3i;
        __syncthreads();
    }

    // ---- unpack real FFT -> power spectrum (1025 bins) into sr ----
    float* __restrict__ pw = sr;
    #pragma unroll
    for (int k = tid; k <= MHALF; k += 256) {
        float v;
        if (k == 0) {
            float x = zr[SK(0)] + zi[SK(0)];
            v = x * x;
        } else if (k == MHALF) {
            float x = zr[SK(0)] - zi[SK(0)];
            v = x * x;
        } else {
            float axr = zr[SK(k)],           axi = zi[SK(k)];
            float cxr = zr[SK(MHALF - k)],   cxi = zi[SK(MHALF - k)];
            float ex = 0.5f * (axr + cxr);
            float ey = 0.5f * (axi - cxi);
            float ox = 0.5f * (axi + cxi);
            float oy = -0.5f * (axr - cxr);
            float2 w = tws[k];
            float xr = ex + ox * w.x - oy * w.y;
            float xi = ey + ox * w.y + oy * w.x;
            v = xr * xr + xi * xi;
        }
        pw[k] = v;
    }
    __syncthreads();

    // ---- sparse triangular mel projection: 2 threads per mel bin ----
    {
        const int m = tid >> 1;
        const int h = tid & 1;
        const float f0 = si[m];
        const float f1 = si[m + 1];
        const float f2 = si[m + 2];
        const float inv_d0 = 1.0f / (f1 - f0);
        const float inv_d1 = 1.0f / (f2 - f1);
        const float df = 16000.0f / 1024.0f;
        int klo = max(0, (int)(f0 / df));
        int khi = min(1024, (int)(f2 / df) + 1);
        float acc = 0.0f;
        for (int k = klo + h; k <= khi; k += 2) {
            float freq = (float)k * df;
            float w = fminf((freq - f0) * inv_d0, (f2 - freq) * inv_d1);
            w = fmaxf(w, 0.0f);
            acc = fmaf(pw[k], w, acc);
        }
        acc += __shfl_xor_sync(0xffffffffu, acc, 1);
        if (h == 0)
            g_mel[((size_t)b * NFRM + t) * NMELS + m] = acc;
    }
}

// ---------------- PCEN: sequential scan over t, one thread per (b,m) ----------------
__global__ __launch_bounds__(128) void pcen_kernel(float* __restrict__ out) {
    const int b = blockIdx.x;
    const int m = threadIdx.x;
    const float S = 0.025f;
    const float ONE_MS = 0.975f;
    const float EPS = 1e-6f;
    const float ALPHA = 0.98f;
    const float DELTA = 2.0f;
    const float DELTA_R = 1.41421356237309515f;  // 2^0.5

    float mst = 0.0f;
    const float* __restrict__ src = g_mel + (size_t)b * NFRM * NMELS + m;
    float* __restrict__ dst = out + ((size_t)b * NMELS + m) * NFRM;

    for (int t = 0; t < NFRM; t++) {
        float x = src[(size_t)t * NMELS];
        mst = fmaf(ONE_MS, mst, S * x);
        float p = sqrtf(x * __powf(EPS + mst, -ALPHA) + DELTA) - DELTA_R;
        dst[t] = p;
    }
}

extern "C" void kernel_launch(void* const* d_in, const int* in_sizes, int n_in,
                              void* d_out, int out_size) {
    const float* wave = (const float*)d_in[0];
    float* out = (float*)d_out;
    dim3 grid(NFRM, BATCH);
    melspec_kernel<<<grid, 256>>>(wave);
    pcen_kernel<<<BATCH, NMELS>>>(out);
}

// round 4
// speedup vs baseline: 2.4630x; 1.4295x over previous
#include <cuda_runtime.h>
#include <math.h>

#define BATCH 64
#define WLEN  160000
#define NFRM  313          // 1 + 160000/512
#define HOP   512
#define NFFT  2048
#define MHALF 1024         // complex FFT length
#define NMELS 128
#define NPTS  130          // mel breakpoints

#define SK(i) ((i) + ((i) >> 3))     // bank-conflict skew
#define ZLEN  (1024 + 128)           // skewed array length

#define NCHUNK 8
#define CHLEN  40                    // 7*40 + 33 = 313

__device__ float g_mel[BATCH * NFRM * NMELS];    // mel power, layout [b][t][m]
__device__ float g_part[BATCH * NCHUNK * NMELS]; // per-chunk partial IIR sums

__device__ __forceinline__ float2 cmul(float2 a, float2 b) {
    return make_float2(a.x * b.x - a.y * b.y, a.x * b.y + a.y * b.x);
}

__device__ __forceinline__ float sqrt_approx(float x) {
    float r;
    asm("sqrt.approx.f32 %0, %1;" : "=f"(r) : "f"(x));
    return r;
}
__device__ __forceinline__ float lg2_approx(float x) {
    float r;
    asm("lg2.approx.f32 %0, %1;" : "=f"(r) : "f"(x));
    return r;
}
__device__ __forceinline__ float ex2_approx(float x) {
    float r;
    asm("ex2.approx.f32 %0, %1;" : "=f"(r) : "f"(x));
    return r;
}

// ---------------- fused frame+window+FFT+power+mel ----------------
// one block per (frame t, batch b); 256 threads; radix-4 DIT 1024-pt complex FFT
__global__ __launch_bounds__(256) void melspec_kernel(const float* __restrict__ wave) {
    __shared__ float  sr[ZLEN];      // staging re -> reused as power spectrum
    __shared__ float  si[ZLEN];      // staging im -> reused as mel breakpoints
    __shared__ float  zr[ZLEN];
    __shared__ float  zi[ZLEN];
    __shared__ float2 tws[MHALF];    // W_2048^k

    const int t   = blockIdx.x;
    const int b   = blockIdx.y;
    const int tid = threadIdx.x;
    const float* __restrict__ wb = wave + (size_t)b * WLEN;

    // ---- build twiddle table (4 __sincosf per thread) ----
    const float ANG = -(float)M_PI / 1024.0f;   // -2*pi/2048
    #pragma unroll
    for (int i = tid; i < MHALF; i += 256) {
        float s, c;
        __sincosf(ANG * (float)i, &s, &c);
        tws[i] = make_float2(c, s);
    }

    // ---- load frame (reflect pad) * Hann, pack 2 reals -> complex, natural order ----
    const int p0 = t * HOP - (NFFT / 2);
    const float CW = (float)M_PI / 1024.0f;     // window angle per sample
    if (p0 >= 0 && p0 + NFFT <= WLEN) {
        const float2* __restrict__ wv = (const float2*)(wb + p0);
        #pragma unroll
        for (int n = tid; n < MHALF; n += 256) {
            float2 v = wv[n];
            float a0 = CW * (float)(2 * n);
            float w0 = 0.5f - 0.5f * __cosf(a0);
            float w1 = 0.5f - 0.5f * __cosf(a0 + CW);
            sr[SK(n)] = v.x * w0;
            si[SK(n)] = v.y * w1;
        }
    } else {
        #pragma unroll
        for (int n = tid; n < NFFT; n += 256) {
            int j = p0 + n;
            int r = (j < 0) ? -j : ((j >= WLEN) ? 2 * WLEN - 2 - j : j);
            float w = 0.5f - 0.5f * __cosf(CW * (float)n);
            float v = wb[r] * w;
            if (n & 1) si[SK(n >> 1)] = v;
            else       sr[SK(n >> 1)] = v;
        }
    }
    __syncthreads();

    // ---- stage 0 (fused with digit-reversed gather; twiddle-free) ----
    {
        unsigned rj = __brev((unsigned)tid) >> 24;              // 8-bit reverse of tid
        rj = ((rj & 0x55u) << 1) | ((rj >> 1) & 0x55u);         // base-4 digit reverse
        float ar[4], ai[4];
        #pragma unroll
        for (int q = 0; q < 4; q++) {
            int idx = (q << 8) + (int)rj;
            ar[q] = sr[SK(idx)];
            ai[q] = si[SK(idx)];
        }
        float t0r = ar[0] + ar[2], t0i = ai[0] + ai[2];
        float t1r = ar[0] - ar[2], t1i = ai[0] - ai[2];
        float t2r = ar[1] + ar[3], t2i = ai[1] + ai[3];
        float t3r = ai[1] - ai[3], t3i = -(ar[1] - ar[3]);      // -i*(a1-a3)
        int o = 4 * tid;
        zr[SK(o + 0)] = t0r + t2r;  zi[SK(o + 0)] = t0i + t2i;
        zr[SK(o + 1)] = t1r + t3r;  zi[SK(o + 1)] = t1i + t3i;
        zr[SK(o + 2)] = t0r - t2r;  zi[SK(o + 2)] = t0i - t2i;
        zr[SK(o + 3)] = t1r - t3r;  zi[SK(o + 3)] = t1i - t3i;
    }
    __syncthreads();

    // ---- mel breakpoints into si (dead after stage 0) ----
    if (tid < NPTS) {
        const float mlo = 2595.0f * log10f(1.0f + 20.0f / 700.0f);
        const float mhi = 2595.0f * log10(1.0f + 16000.0f / 700.0f);
        float m = mlo + (mhi - mlo) * (float)tid / (float)(NPTS - 1);
        si[tid] = 700.0f * (exp10f(m / 2595.0f) - 1.0f);
    }

    // ---- stages 1..4 (radix-4 DIT) ----
    #pragma unroll
    for (int s = 1; s < 5; s++) {
        const int quarter = 1 << (2 * s);
        const int pos = tid & (quarter - 1);
        const int i0  = ((tid >> (2 * s)) << (2 * s + 2)) + pos;
        float2 w1 = tws[pos << (9 - 2 * s)];
        float2 w2 = cmul(w1, w1);
        float2 w3 = cmul(w2, w1);

        float ar[4], ai[4];
        #pragma unroll
        for (int q = 0; q < 4; q++) {
            int idx = i0 + q * quarter;
            ar[q] = zr[SK(idx)];
            ai[q] = zi[SK(idx)];
        }
        float b1r = ar[1] * w1.x - ai[1] * w1.y, b1i = ar[1] * w1.y + ai[1] * w1.x;
        float b2r = ar[2] * w2.x - ai[2] * w2.y, b2i = ar[2] * w2.y + ai[2] * w2.x;
        float b3r = ar[3] * w3.x - ai[3] * w3.y, b3i = ar[3] * w3.y + ai[3] * w3.x;

        float t0r = ar[0] + b2r, t0i = ai[0] + b2i;
        float t1r = ar[0] - b2r, t1i = ai[0] - b2i;
        float t2r = b1r + b3r,   t2i = b1i + b3i;
        float t3r = b1i - b3i,   t3i = -(b1r - b3r);            // -i*(b1-b3)

        __syncthreads();
        zr[SK(i0)]               = t0r + t2r;  zi[SK(i0)]               = t0i + t2i;
        zr[SK(i0 + quarter)]     = t1r + t3r;  zi[SK(i0 + quarter)]     = t1i + t3i;
        zr[SK(i0 + 2 * quarter)] = t0r - t2r;  zi[SK(i0 + 2 * quarter)] = t0i - t2i;
        zr[SK(i0 + 3 * quarter)] = t1r - t3r;  zi[SK(i0 + 3 * quarter)] = t1i - t3i;
        __syncthreads();
    }

    // ---- unpack real FFT -> power spectrum (1025 bins) into sr ----
    float* __restrict__ pw = sr;
    #pragma unroll
    for (int k = tid; k <= MHALF; k += 256) {
        float v;
        if (k == 0) {
            float x = zr[SK(0)] + zi[SK(0)];
            v = x * x;
        } else if (k == MHALF) {
            float x = zr[SK(0)] - zi[SK(0)];
            v = x * x;
        } else {
            float axr = zr[SK(k)],           axi = zi[SK(k)];
            float cxr = zr[SK(MHALF - k)],   cxi = zi[SK(MHALF - k)];
            float ex = 0.5f * (axr + cxr);
            float ey = 0.5f * (axi - cxi);
            float ox = 0.5f * (axi + cxi);
            float oy = -0.5f * (axr - cxr);
            float2 w = tws[k];
            float xr = ex + ox * w.x - oy * w.y;
            float xi = ey + ox * w.y + oy * w.x;
            v = xr * xr + xi * xi;
        }
        pw[k] = v;
    }
    __syncthreads();

    // ---- sparse triangular mel projection: 2 threads per mel bin ----
    {
        const int m = tid >> 1;
        const int h = tid & 1;
        const float f0 = si[m];
        const float f1 = si[m + 1];
        const float f2 = si[m + 2];
        const float inv_d0 = 1.0f / (f1 - f0);
        const float inv_d1 = 1.0f / (f2 - f1);
        const float df = 16000.0f / 1024.0f;
        int klo = max(0, (int)(f0 / df));
        int khi = min(1024, (int)(f2 / df) + 1);
        float acc = 0.0f;
        for (int k = klo + h; k <= khi; k += 2) {
            float freq = (float)k * df;
            float w = fminf((freq - f0) * inv_d0, (f2 - freq) * inv_d1);
            w = fmaxf(w, 0.0f);
            acc = fmaf(pw[k], w, acc);
        }
        acc += __shfl_xor_sync(0xffffffffu, acc, 1);
        if (h == 0)
            g_mel[((size_t)b * NFRM + t) * NMELS + m] = acc;
    }
}

// ---------------- PCEN pass A: per-chunk partial IIR (m0 = 0) ----------------
__global__ __launch_bounds__(128) void pcen_partial_kernel() {
    const int b = blockIdx.x;
    const int c = blockIdx.y;
    const int m = threadIdx.x;
    const int t0 = c * CHLEN;
    const int len = min(CHLEN, NFRM - t0);

    const float* __restrict__ src = g_mel + ((size_t)b * NFRM + t0) * NMELS + m;
    float p = 0.0f;
    for (int k = 0; k < len; k++) {
        float x = src[(size_t)k * NMELS];
        p = fmaf(0.975f, p, 0.025f * x);
    }
    g_part[((size_t)b * NCHUNK + c) * NMELS + m] = p;
}

// ---------------- PCEN pass B: reconstruct state, emit outputs ----------------
__global__ __launch_bounds__(128) void pcen_out_kernel(float* __restrict__ out) {
    __shared__ float sm[NMELS * (CHLEN + 1)];   // staged outputs, row-padded

    const int b = blockIdx.x;
    const int c = blockIdx.y;
    const int m = threadIdx.x;
    const int t0 = c * CHLEN;
    const int len = min(CHLEN, NFRM - t0);

    // decay across one full chunk: 0.975^40 (exact repeated multiply; cheap)
    float pow40 = 1.0f;
    #pragma unroll
    for (int i = 0; i < CHLEN; i++) pow40 *= 0.975f;

    // chunk-start state: combine earlier chunks' partials
    const float* __restrict__ part = g_part + (size_t)b * NCHUNK * NMELS + m;
    float mst = 0.0f;
    for (int cp = 0; cp < c; cp++)
        mst = fmaf(mst, pow40, part[(size_t)cp * NMELS]);

    const float EPS = 1e-6f;
    const float ALPHA = 0.98f;
    const float DELTA = 2.0f;
    const float DELTA_R = 1.41421356237309515f;  // 2^0.5

    const float* __restrict__ src = g_mel + ((size_t)b * NFRM + t0) * NMELS + m;
    float* __restrict__ row = sm + (size_t)m * (CHLEN + 1);

    for (int k = 0; k < len; k++) {
        float x = src[(size_t)k * NMELS];
        mst = fmaf(0.975f, mst, 0.025f * x);
        float d = ex2_approx(-ALPHA * lg2_approx(EPS + mst));
        row[k] = sqrt_approx(fmaf(x, d, DELTA)) - DELTA_R;
    }
    __syncthreads();

    // coalesced writeback: out layout [b][m][t]
    float* __restrict__ dst = out + (size_t)b * NMELS * NFRM + t0;
    const int total = NMELS * len;
    for (int j = m; j < total; j += NMELS) {
        int mr = j / len;
        int tt = j - mr * len;
        dst[(size_t)mr * NFRM + tt] = sm[(size_t)mr * (CHLEN + 1) + tt];
    }
}

extern "C" void kernel_launch(void* const* d_in, const int* in_sizes, int n_in,
                              void* d_out, int out_size) {
    const float* wave = (const float*)d_in[0];
    float* out = (float*)d_out;

    dim3 grid(NFRM, BATCH);
    melspec_kernel<<<grid, 256>>>(wave);

    dim3 pgrid(BATCH, NCHUNK);
    pcen_partial_kernel<<<pgrid, NMELS>>>();
    pcen_out_kernel<<<pgrid, NMELS>>>(out);
}

// round 5
// speedup vs baseline: 3.8992x; 1.5831x over previous
#include <cuda_runtime.h>
#include <math.h>

#define BATCH 64
#define WLEN  160000
#define NFRM  313          // 1 + 160000/512
#define HOP   512
#define NFFT  2048
#define MHALF 1024         // complex FFT length
#define NMELS 128
#define NPTS  130          // mel breakpoints

#define SK(i) ((i) + ((i) >> 5))     // pad-32 skew: conflict-free for stride 16/256
#define ZLEN  1088                   // >= SK(1024)+1 = 1057

#define NCHUNK 8
#define CHLEN  40                    // 7*40 + 33 = 313

__device__ float g_mel[BATCH * NFRM * NMELS];    // mel power, layout [b][t][m]
__device__ float g_part[BATCH * NCHUNK * NMELS]; // per-chunk partial IIR sums

__device__ __forceinline__ float2 cmul(float2 a, float2 b) {
    return make_float2(a.x * b.x - a.y * b.y, a.x * b.y + a.y * b.x);
}
__device__ __forceinline__ float sqrt_approx(float x) {
    float r; asm("sqrt.approx.f32 %0, %1;" : "=f"(r) : "f"(x)); return r;
}
__device__ __forceinline__ float lg2_approx(float x) {
    float r; asm("lg2.approx.f32 %0, %1;" : "=f"(r) : "f"(x)); return r;
}
__device__ __forceinline__ float ex2_approx(float x) {
    float r; asm("ex2.approx.f32 %0, %1;" : "=f"(r) : "f"(x)); return r;
}

// radix-4 DIT butterfly: inputs a0..a3 (a_q), twiddles w1,w2,w3 applied to a1,a2,a3.
// outputs written back: slot q gets q-th output (matches i0 + q*quarter layout).
__device__ __forceinline__ void radix4(float2& a0, float2& a1, float2& a2, float2& a3,
                                       float2 w1, float2 w2, float2 w3) {
    float2 b1 = cmul(a1, w1);
    float2 b2 = cmul(a2, w2);
    float2 b3 = cmul(a3, w3);
    float t0r = a0.x + b2.x, t0i = a0.y + b2.y;
    float t1r = a0.x - b2.x, t1i = a0.y - b2.y;
    float t2r = b1.x + b3.x, t2i = b1.y + b3.y;
    float t3r = b1.y - b3.y, t3i = -(b1.x - b3.x);   // -i*(b1-b3)
    a0 = make_float2(t0r + t2r, t0i + t2i);
    a1 = make_float2(t1r + t3r, t1i + t3i);
    a2 = make_float2(t0r - t2r, t0i - t2i);
    a3 = make_float2(t1r - t3r, t1i - t3i);
}
// twiddle-free radix-4 (stage 0)
__device__ __forceinline__ void radix4_nt(float2& a0, float2& a1, float2& a2, float2& a3) {
    float t0r = a0.x + a2.x, t0i = a0.y + a2.y;
    float t1r = a0.x - a2.x, t1i = a0.y - a2.y;
    float t2r = a1.x + a3.x, t2i = a1.y + a3.y;
    float t3r = a1.y - a3.y, t3i = -(a1.x - a3.x);
    a0 = make_float2(t0r + t2r, t0i + t2i);
    a1 = make_float2(t1r + t3r, t1i + t3i);
    a2 = make_float2(t0r - t2r, t0i - t2i);
    a3 = make_float2(t1r - t3r, t1i - t3i);
}

// ---------------- fused frame+window+FFT+power+mel ----------------
// 256 threads = 4 frames x 64 threads; 16 complex points per thread.
// FFT: merged radix-4 stage pairs [0+1], [2+3], then stage 4. 3 smem round trips.
__global__ __launch_bounds__(256, 3) void melspec_kernel(const float* __restrict__ wave) {
    __shared__ float zr[4][ZLEN];
    __shared__ float zi[4][ZLEN];
    __shared__ float fp[NPTS];

    const int tid = threadIdx.x;
    const int f   = tid >> 6;          // frame within block
    const int T   = tid & 63;          // thread within frame
    const int g   = blockIdx.x * 4 + f;
    const int b   = g / NFRM;
    const int t   = g - b * NFRM;

    float* __restrict__ Zr = zr[f];
    float* __restrict__ Zi = zi[f];

    // mel breakpoints (used at the very end; any later sync orders this)
    if (tid < NPTS) {
        const float mlo = 2595.0f * log10f(1.0f + 20.0f / 700.0f);
        const float mhi = 2595.0f * log10f(1.0f + 16000.0f / 700.0f);
        float m = mlo + (mhi - mlo) * (float)tid / (float)(NPTS - 1);
        fp[tid] = 700.0f * (exp10f(m / 2595.0f) - 1.0f);
    }

    // ---- staging: frame (reflect pad) * Hann, 2 reals -> 1 complex, natural order ----
    const float* __restrict__ wb = wave + (size_t)b * WLEN;
    const int p0 = t * HOP - (NFFT / 2);
    const float CW = (float)M_PI / 1024.0f;     // window angle per real sample
    if (p0 >= 0 && p0 + NFFT <= WLEN) {
        const float2* __restrict__ wv = (const float2*)(wb + p0);
        #pragma unroll
        for (int e = 0; e < 16; e++) {
            int n = T + 64 * e;
            float2 v = wv[n];
            float a0 = CW * (float)(2 * n);
            float w0 = 0.5f - 0.5f * __cosf(a0);
            float w1 = 0.5f - 0.5f * __cosf(a0 + CW);
            Zr[SK(n)] = v.x * w0;
            Zi[SK(n)] = v.y * w1;
        }
    } else {
        #pragma unroll
        for (int e = 0; e < 16; e++) {
            int n = T + 64 * e;
            int j0 = p0 + 2 * n;
            int j1 = j0 + 1;
            int r0 = (j0 < 0) ? -j0 : ((j0 >= WLEN) ? 2 * WLEN - 2 - j0 : j0);
            int r1 = (j1 < 0) ? -j1 : ((j1 >= WLEN) ? 2 * WLEN - 2 - j1 : j1);
            float a0 = CW * (float)(2 * n);
            Zr[SK(n)] = wb[r0] * (0.5f - 0.5f * __cosf(a0));
            Zi[SK(n)] = wb[r1] * (0.5f - 0.5f * __cosf(a0 + CW));
        }
    }
    __syncthreads();

    // ---- merged stages 0+1: outputs [16T, 16T+16) ----
    {
        float2 y[4][4];   // y[j][r]
        #pragma unroll
        for (int j = 0; j < 4; j++) {
            unsigned old = (unsigned)(4 * T + j);
            unsigned rj = __brev(old) >> 24;
            rj = ((rj & 0x55u) << 1) | ((rj >> 1) & 0x55u);   // base-4 digit reverse
            float2 a0 = make_float2(Zr[SK(rj)],       Zi[SK(rj)]);
            float2 a1 = make_float2(Zr[SK(rj + 256)], Zi[SK(rj + 256)]);
            float2 a2 = make_float2(Zr[SK(rj + 512)], Zi[SK(rj + 512)]);
            float2 a3 = make_float2(Zr[SK(rj + 768)], Zi[SK(rj + 768)]);
            radix4_nt(a0, a1, a2, a3);
            y[j][0] = a0; y[j][1] = a1; y[j][2] = a2; y[j][3] = a3;
        }
        __syncthreads();   // all gathers complete block-wide before any store

        // stage 1: butterfly over j (=q) for each p, twiddles W16^p (constants)
        const float2 W16_1[4] = { {1.f,0.f}, {0.92387953251f,-0.38268343236f},
                                  {0.70710678119f,-0.70710678119f}, {0.38268343236f,-0.92387953251f} };
        const float2 W16_2[4] = { {1.f,0.f}, {0.70710678119f,-0.70710678119f},
                                  {0.f,-1.f}, {-0.70710678119f,-0.70710678119f} };
        const float2 W16_3[4] = { {1.f,0.f}, {0.38268343236f,-0.92387953251f},
                                  {-0.70710678119f,-0.70710678119f}, {-0.92387953251f,0.38268343236f} };
        #pragma unroll
        for (int p = 0; p < 4; p++)
            radix4(y[0][p], y[1][p], y[2][p], y[3][p], W16_1[p], W16_2[p], W16_3[p]);

        #pragma unroll
        for (int q = 0; q < 4; q++)
            #pragma unroll
            for (int p = 0; p < 4; p++) {
                int idx = 16 * T + p + 4 * q;
                Zr[SK(idx)] = y[q][p].x;
                Zi[SK(idx)] = y[q][p].y;
            }
    }
    __syncthreads();

    // ---- merged stages 2+3: thread owns {256C + 16u + j0, u=0..15}, in place ----
    {
        const int C  = T >> 4;
        const int j0 = T & 15;
        const int base = 256 * C + j0;
        float2 v[16];
        #pragma unroll
        for (int u = 0; u < 16; u++) {
            int idx = base + 16 * u;
            v[u] = make_float2(Zr[SK(idx)], Zi[SK(idx)]);
        }
        // stage 2: twiddle exp(-2*pi*i*j0/64), same for all 4 sub-butterflies
        {
            float s, c;
            __sincosf(-2.0f * (float)M_PI * (float)j0 / 64.0f, &s, &c);
            float2 w1 = make_float2(c, s);
            float2 w2 = cmul(w1, w1);
            float2 w3 = cmul(w2, w1);
            #pragma unroll
            for (int a = 0; a < 4; a++)
                radix4(v[4*a+0], v[4*a+1], v[4*a+2], v[4*a+3], w1, w2, w3);
        }
        // stage 3: twiddle exp(-2*pi*i*(16b+j0)/256) per b
        #pragma unroll
        for (int bq = 0; bq < 4; bq++) {
            float s, c;
            __sincosf(-2.0f * (float)M_PI * (float)(16 * bq + j0) / 256.0f, &s, &c);
            float2 w1 = make_float2(c, s);
            float2 w2 = cmul(w1, w1);
            float2 w3 = cmul(w2, w1);
            radix4(v[bq], v[4+bq], v[8+bq], v[12+bq], w1, w2, w3);
        }
        #pragma unroll
        for (int u = 0; u < 16; u++) {
            int idx = base + 16 * u;
            Zr[SK(idx)] = v[u].x;
            Zi[SK(idx)] = v[u].y;
        }
    }
    __syncthreads();

    // ---- stage 4: thread owns {4T+d + 256q}, in place ----
    {
        #pragma unroll
        for (int d = 0; d < 4; d++) {
            int pos = 4 * T + d;
            float2 a0 = make_float2(Zr[SK(pos)],       Zi[SK(pos)]);
            float2 a1 = make_float2(Zr[SK(pos + 256)], Zi[SK(pos + 256)]);
            float2 a2 = make_float2(Zr[SK(pos + 512)], Zi[SK(pos + 512)]);
            float2 a3 = make_float2(Zr[SK(pos + 768)], Zi[SK(pos + 768)]);
            float s, c;
            __sincosf(-2.0f * (float)M_PI * (float)pos / 1024.0f, &s, &c);
            float2 w1 = make_float2(c, s);
            float2 w2 = cmul(w1, w1);
            float2 w3 = cmul(w2, w1);
            radix4(a0, a1, a2, a3, w1, w2, w3);
            Zr[SK(pos)]       = a0.x;  Zi[SK(pos)]       = a0.y;
            Zr[SK(pos + 256)] = a1.x;  Zi[SK(pos + 256)] = a1.y;
            Zr[SK(pos + 512)] = a2.x;  Zi[SK(pos + 512)] = a2.y;
            Zr[SK(pos + 768)] = a3.x;  Zi[SK(pos + 768)] = a3.y;
        }
    }
    __syncthreads();

    // ---- real-FFT unpack -> power, written IN PLACE over Zr ----
    // thread T handles k = T + 64e, e = 0..7 (k in [0,512)); each k also yields pw[1024-k].
    // 2 rounds of 4 bins with reg buffering; round r reads are disjoint from
    // round <r writes ([0,256)+(768,1024] first, then [256,768]).
    {
        // rotor w(k) = exp(-i*pi*k/1024), advanced by exp(-i*pi/16) per e-step
        float ws, wc;
        __sincosf(-(float)M_PI * (float)T / 1024.0f, &ws, &wc);
        float2 w = make_float2(wc, ws);
        const float2 WSTEP = make_float2(0.98078528040f, -0.19509032202f);  // exp(-i*pi/16)

        #pragma unroll
        for (int r = 0; r < 2; r++) {
            float2 la[4], lc[4], wsv[4];
            float z512r = 0.f, z512i = 0.f;
            #pragma unroll
            for (int ee = 0; ee < 4; ee++) {
                int k = T + 64 * (4 * r + ee);
                wsv[ee] = w;
                if (k == 0) {
                    la[ee] = make_float2(Zr[SK(0)], Zi[SK(0)]);
                    lc[ee] = la[ee];
                } else {
                    la[ee] = make_float2(Zr[SK(k)],        Zi[SK(k)]);
                    lc[ee] = make_float2(Zr[SK(1024 - k)], Zi[SK(1024 - k)]);
                }
                w = cmul(w, WSTEP);
            }
            if (T == 0 && r == 1) { z512r = Zr[SK(512)]; z512i = Zi[SK(512)]; }
            __syncthreads();
            #pragma unroll
            for (int ee = 0; ee < 4; ee++) {
                int k = T + 64 * (4 * r + ee);
                if (k == 0) {
                    float x0 = la[ee].x + la[ee].y;
                    float x1 = la[ee].x - la[ee].y;
                    Zr[SK(0)]    = x0 * x0;   // pw[0]
                    Zr[SK(1024)] = x1 * x1;   // pw[1024]
                } else {
                    float2 a = la[ee], cc = lc[ee], wk = wsv[ee];
                    float ex = 0.5f * (a.x + cc.x);
                    float ey = 0.5f * (a.y - cc.y);
                    float ox = 0.5f * (a.y + cc.y);
                    float oy = -0.5f * (a.x - cc.x);
                    float xr = ex + ox * wk.x - oy * wk.y;
                    float xi = ey + ox * wk.y + oy * wk.x;
                    Zr[SK(k)] = xr * xr + xi * xi;              // pw[k]
                    float x2r = ex - ox * wk.x + oy * wk.y;     // pw[1024-k]
                    float x2i = -ey + ox * wk.y + oy * wk.x;
                    Zr[SK(1024 - k)] = x2r * x2r + x2i * x2i;
                }
            }
            if (T == 0 && r == 1) Zr[SK(512)] = z512r * z512r + z512i * z512i;
            __syncthreads();
        }
    }

    // ---- sparse triangular mel projection: thread T does mels T and T+64 ----
    {
        const float df = 16000.0f / 1024.0f;
        #pragma unroll
        for (int h = 0; h < 2; h++) {
            int m = T + 64 * h;
            float f0 = fp[m];
            float f1 = fp[m + 1];
            float f2 = fp[m + 2];
            float inv_d0 = 1.0f / (f1 - f0);
            float inv_d1 = 1.0f / (f2 - f1);
            int klo = max(0, (int)(f0 / df));
            int khi = min(1024, (int)(f2 / df) + 1);
            float acc = 0.0f;
            for (int k = klo; k <= khi; k++) {
                float freq = (float)k * df;
                float wgt = fminf((freq - f0) * inv_d0, (f2 - freq) * inv_d1);
                wgt = fmaxf(wgt, 0.0f);
                acc = fmaf(Zr[SK(k)], wgt, acc);
            }
            g_mel[((size_t)b * NFRM + t) * NMELS + m] = acc;
        }
    }
}

// ---------------- PCEN pass A: per-chunk partial IIR (m0 = 0) ----------------
__global__ __launch_bounds__(128) void pcen_partial_kernel() {
    const int b = blockIdx.x;
    const int c = blockIdx.y;
    const int m = threadIdx.x;
    const int t0 = c * CHLEN;
    const int len = min(CHLEN, NFRM - t0);

    const float* __restrict__ src = g_mel + ((size_t)b * NFRM + t0) * NMELS + m;
    float p = 0.0f;
    for (int k = 0; k < len; k++) {
        float x = src[(size_t)k * NMELS];
        p = fmaf(0.975f, p, 0.025f * x);
    }
    g_part[((size_t)b * NCHUNK + c) * NMELS + m] = p;
}

// ---------------- PCEN pass B: reconstruct state, emit outputs ----------------
__global__ __launch_bounds__(128) void pcen_out_kernel(float* __restrict__ out) {
    __shared__ float sm[NMELS * (CHLEN + 1)];

    const int b = blockIdx.x;
    const int c = blockIdx.y;
    const int m = threadIdx.x;
    const int t0 = c * CHLEN;
    const int len = min(CHLEN, NFRM - t0);

    float pow40 = 1.0f;
    #pragma unroll
    for (int i = 0; i < CHLEN; i++) pow40 *= 0.975f;

    const float* __restrict__ part = g_part + (size_t)b * NCHUNK * NMELS + m;
    float mst = 0.0f;
    for (int cp = 0; cp < c; cp++)
        mst = fmaf(mst, pow40, part[(size_t)cp * NMELS]);

    const float EPS = 1e-6f;
    const float ALPHA = 0.98f;
    const float DELTA = 2.0f;
    const float DELTA_R = 1.41421356237309515f;

    const float* __restrict__ src = g_mel + ((size_t)b * NFRM + t0) * NMELS + m;
    float* __restrict__ row = sm + (size_t)m * (CHLEN + 1);

    for (int k = 0; k < len; k++) {
        float x = src[(size_t)k * NMELS];
        mst = fmaf(0.975f, mst, 0.025f * x);
        float d = ex2_approx(-ALPHA * lg2_approx(EPS + mst));
        row[k] = sqrt_approx(fmaf(x, d, DELTA)) - DELTA_R;
    }
    __syncthreads();

    float* __restrict__ dst = out + (size_t)b * NMELS * NFRM + t0;
    const int total = NMELS * len;
    for (int j = m; j < total; j += NMELS) {
        int mr = j / len;
        int tt = j - mr * len;
        dst[(size_t)mr * NFRM + tt] = sm[(size_t)mr * (CHLEN + 1) + tt];
    }
}

extern "C" void kernel_launch(void* const* d_in, const int* in_sizes, int n_in,
                              void* d_out, int out_size) {
    const float* wave = (const float*)d_in[0];
    float* out = (float*)d_out;

    melspec_kernel<<<(BATCH * NFRM) / 4, 256>>>(wave);   // 20032/4 = 5008 blocks

    dim3 pgrid(BATCH, NCHUNK);
    pcen_partial_kernel<<<pgrid, NMELS>>>();
    pcen_out_kernel<<<pgrid, NMELS>>>(out);
}

// round 6
// speedup vs baseline: 4.0442x; 1.0372x over previous
#include <cuda_runtime.h>
#include <math.h>

#define BATCH 64
#define WLEN  160000
#define NFRM  313          // 1 + 160000/512
#define HOP   512
#define NFFT  2048
#define MHALF 1024         // complex FFT length
#define NMELS 128
#define NPTS  130          // mel breakpoints

#define SK2(i) ((i) + ((i) >> 4))    // float2 skew: conflict-free for stride 1/4/16/256 + digit-rev
#define ZLEN2  1092                  // >= SK2(1023)+1 = 1087

#define NCHUNK 8
#define CHLEN  40                    // 7*40 + 33 = 313

__device__ float g_mel[BATCH * NFRM * NMELS];    // mel power, layout [b][t][m]
__device__ float g_part[BATCH * NCHUNK * NMELS]; // per-chunk partial IIR sums

__device__ __forceinline__ float2 cmul(float2 a, float2 b) {
    return make_float2(a.x * b.x - a.y * b.y, a.x * b.y + a.y * b.x);
}
__device__ __forceinline__ float sqrt_approx(float x) {
    float r; asm("sqrt.approx.f32 %0, %1;" : "=f"(r) : "f"(x)); return r;
}
__device__ __forceinline__ float lg2_approx(float x) {
    float r; asm("lg2.approx.f32 %0, %1;" : "=f"(r) : "f"(x)); return r;
}
__device__ __forceinline__ float ex2_approx(float x) {
    float r; asm("ex2.approx.f32 %0, %1;" : "=f"(r) : "f"(x)); return r;
}

// radix-4 DIT butterfly with twiddles on a1..a3; slot q receives q-th output.
__device__ __forceinline__ void radix4(float2& a0, float2& a1, float2& a2, float2& a3,
                                       float2 w1, float2 w2, float2 w3) {
    float2 b1 = cmul(a1, w1);
    float2 b2 = cmul(a2, w2);
    float2 b3 = cmul(a3, w3);
    float t0r = a0.x + b2.x, t0i = a0.y + b2.y;
    float t1r = a0.x - b2.x, t1i = a0.y - b2.y;
    float t2r = b1.x + b3.x, t2i = b1.y + b3.y;
    float t3r = b1.y - b3.y, t3i = -(b1.x - b3.x);   // -i*(b1-b3)
    a0 = make_float2(t0r + t2r, t0i + t2i);
    a1 = make_float2(t1r + t3r, t1i + t3i);
    a2 = make_float2(t0r - t2r, t0i - t2i);
    a3 = make_float2(t1r - t3r, t1i - t3i);
}
__device__ __forceinline__ void radix4_nt(float2& a0, float2& a1, float2& a2, float2& a3) {
    float t0r = a0.x + a2.x, t0i = a0.y + a2.y;
    float t1r = a0.x - a2.x, t1i = a0.y - a2.y;
    float t2r = a1.x + a3.x, t2i = a1.y + a3.y;
    float t3r = a1.y - a3.y, t3i = -(a1.x - a3.x);
    a0 = make_float2(t0r + t2r, t0i + t2i);
    a1 = make_float2(t1r + t3r, t1i + t3i);
    a2 = make_float2(t0r - t2r, t0i - t2i);
    a3 = make_float2(t1r - t3r, t1i - t3i);
}

// ---------------- fused frame+window+FFT+power+mel ----------------
// 256 threads = 4 frames x 64 threads; 16 complex points per thread.
__global__ __launch_bounds__(256, 3) void melspec_kernel(const float* __restrict__ wave) {
    __shared__ float2 zz[4][ZLEN2];
    __shared__ float  fp[NPTS];

    const int tid = threadIdx.x;
    const int f   = tid >> 6;          // frame within block
    const int T   = tid & 63;          // thread within frame
    const int g   = blockIdx.x * 4 + f;
    const int b   = g / NFRM;
    const int t   = g - b * NFRM;

    float2* __restrict__ Zz = zz[f];

    // mel breakpoints (consumed at the end; ordered by later syncs)
    if (tid < NPTS) {
        const float mlo = 2595.0f * log10f(1.0f + 20.0f / 700.0f);
        const float mhi = 2595.0f * log10f(1.0f + 16000.0f / 700.0f);
        float m = mlo + (mhi - mlo) * (float)tid / (float)(NPTS - 1);
        fp[tid] = 700.0f * (exp10f(m / 2595.0f) - 1.0f);
    }

    // ---- staging: frame (reflect pad) * Hann; window via rotor recurrence ----
    const float* __restrict__ wb = wave + (size_t)b * WLEN;
    const int p0 = t * HOP - (NFFT / 2);
    const float CW = (float)M_PI / 1024.0f;     // angle per real sample
    // rotor at a0 = CW*2T, advanced by pi/8 per e; cos(a0+CW) via constant rotation
    float rs, rc;
    __sincosf(CW * (float)(2 * T), &rs, &rc);
    float2 rot = make_float2(rc, rs);
    const float2 RSTEP = make_float2(0.9238795325112867f, 0.3826834323650898f);   // exp(+i pi/8)
    const float CCW = 0.9999952938095760f;   // cos(pi/1024)
    const float SCW = 0.0030679567629659760f; // sin(pi/1024)

    if (p0 >= 0 && p0 + NFFT <= WLEN) {
        const float2* __restrict__ wv = (const float2*)(wb + p0);
        #pragma unroll
        for (int e = 0; e < 16; e++) {
            int n = T + 64 * e;
            float2 v = wv[n];
            float c1 = rot.x * CCW - rot.y * SCW;
            float w0 = 0.5f - 0.5f * rot.x;
            float w1 = 0.5f - 0.5f * c1;
            Zz[SK2(n)] = make_float2(v.x * w0, v.y * w1);
            rot = cmul(rot, RSTEP);
        }
    } else {
        #pragma unroll
        for (int e = 0; e < 16; e++) {
            int n = T + 64 * e;
            int j0 = p0 + 2 * n;
            int j1 = j0 + 1;
            int r0 = (j0 < 0) ? -j0 : ((j0 >= WLEN) ? 2 * WLEN - 2 - j0 : j0);
            int r1 = (j1 < 0) ? -j1 : ((j1 >= WLEN) ? 2 * WLEN - 2 - j1 : j1);
            float c1 = rot.x * CCW - rot.y * SCW;
            float w0 = 0.5f - 0.5f * rot.x;
            float w1 = 0.5f - 0.5f * c1;
            Zz[SK2(n)] = make_float2(wb[r0] * w0, wb[r1] * w1);
            rot = cmul(rot, RSTEP);
        }
    }
    __syncthreads();

    // ---- merged stages 0+1: outputs [16T, 16T+16) ----
    {
        float2 y[4][4];   // y[j][p]
        #pragma unroll
        for (int j = 0; j < 4; j++) {
            unsigned old = (unsigned)(4 * T + j);
            unsigned rj = __brev(old) >> 24;
            rj = ((rj & 0x55u) << 1) | ((rj >> 1) & 0x55u);   // base-4 digit reverse
            float2 a0 = Zz[SK2(rj)];
            float2 a1 = Zz[SK2(rj + 256)];
            float2 a2 = Zz[SK2(rj + 512)];
            float2 a3 = Zz[SK2(rj + 768)];
            radix4_nt(a0, a1, a2, a3);
            y[j][0] = a0; y[j][1] = a1; y[j][2] = a2; y[j][3] = a3;
        }
        __syncthreads();   // all gathers complete block-wide before any store

        const float2 W16_1[4] = { {1.f,0.f}, {0.92387953251f,-0.38268343236f},
                                  {0.70710678119f,-0.70710678119f}, {0.38268343236f,-0.92387953251f} };
        const float2 W16_2[4] = { {1.f,0.f}, {0.70710678119f,-0.70710678119f},
                                  {0.f,-1.f}, {-0.70710678119f,-0.70710678119f} };
        const float2 W16_3[4] = { {1.f,0.f}, {0.38268343236f,-0.92387953251f},
                                  {-0.70710678119f,-0.70710678119f}, {-0.92387953251f,0.38268343236f} };
        #pragma unroll
        for (int p = 0; p < 4; p++)
            radix4(y[0][p], y[1][p], y[2][p], y[3][p], W16_1[p], W16_2[p], W16_3[p]);

        #pragma unroll
        for (int q = 0; q < 4; q++)
            #pragma unroll
            for (int p = 0; p < 4; p++)
                Zz[SK2(16 * T + p + 4 * q)] = y[q][p];
    }
    __syncthreads();

    // ---- merged stages 2+3: thread owns {256C + 16u + j0}, in place ----
    {
        const int C  = T >> 4;
        const int j0 = T & 15;
        const int base = 256 * C + j0;
        float2 v[16];
        #pragma unroll
        for (int u = 0; u < 16; u++)
            v[u] = Zz[SK2(base + 16 * u)];

        // stage 2: twiddle exp(-2*pi*i*j0/64)
        {
            float s, c;
            __sincosf(-(float)M_PI * (float)j0 / 32.0f, &s, &c);
            float2 w1 = make_float2(c, s);
            float2 w2 = cmul(w1, w1);
            float2 w3 = cmul(w2, w1);
            #pragma unroll
            for (int a = 0; a < 4; a++)
                radix4(v[4*a+0], v[4*a+1], v[4*a+2], v[4*a+3], w1, w2, w3);
        }
        // stage 3: w1(bq) = exp(-2*pi*i*(16bq + j0)/256) via rotor
        {
            float s, c;
            __sincosf(-(float)M_PI * (float)j0 / 128.0f, &s, &c);
            float2 w = make_float2(c, s);
            const float2 STEP3 = make_float2(0.9238795325112867f, -0.3826834323650898f); // exp(-i pi/8)
            #pragma unroll
            for (int bq = 0; bq < 4; bq++) {
                float2 w2 = cmul(w, w);
                float2 w3 = cmul(w2, w);
                radix4(v[bq], v[4+bq], v[8+bq], v[12+bq], w, w2, w3);
                w = cmul(w, STEP3);
            }
        }
        #pragma unroll
        for (int u = 0; u < 16; u++)
            Zz[SK2(base + 16 * u)] = v[u];
    }
    __syncthreads();

    // ---- stage 4: thread owns {4T+d + 256q}, in place; twiddle rotor ----
    {
        float s, c;
        __sincosf(-(float)M_PI * (float)T / 128.0f, &s, &c);     // exp(-2pi*i*4T/1024)
        float2 w = make_float2(c, s);
        const float2 STEP4 = make_float2(0.9999811752826011f, -0.0061358846491544753f); // exp(-2pi i/1024)
        #pragma unroll
        for (int d = 0; d < 4; d++) {
            int pos = 4 * T + d;
            float2 a0 = Zz[SK2(pos)];
            float2 a1 = Zz[SK2(pos + 256)];
            float2 a2 = Zz[SK2(pos + 512)];
            float2 a3 = Zz[SK2(pos + 768)];
            float2 w2 = cmul(w, w);
            float2 w3 = cmul(w2, w);
            radix4(a0, a1, a2, a3, w, w2, w3);
            Zz[SK2(pos)]       = a0;
            Zz[SK2(pos + 256)] = a1;
            Zz[SK2(pos + 512)] = a2;
            Zz[SK2(pos + 768)] = a3;
            w = cmul(w, STEP4);
        }
    }
    __syncthreads();

    // ---- real-FFT unpack -> power pairs, IN PLACE over Zz ----
    // slot[k] = (pw[k], pw[1024-k]) for k in [0,512]; thread T covers k = T+64e.
    // round 0: k in [0,256) writes zz[0,272); round 1 reads zz[272,816] -- disjoint.
    {
        float ws, wc;
        __sincosf(-(float)M_PI * (float)T / 1024.0f, &ws, &wc);
        float2 w = make_float2(wc, ws);
        const float2 WSTEP = make_float2(0.9807852804032304f, -0.19509032201612825f);  // exp(-i pi/16)

        #pragma unroll
        for (int r = 0; r < 2; r++) {
            float2 la[4], lc[4], wsv[4];
            float2 z512 = make_float2(0.f, 0.f);
            #pragma unroll
            for (int ee = 0; ee < 4; ee++) {
                int k = T + 64 * (4 * r + ee);
                wsv[ee] = w;
                if (k == 0) { la[ee] = Zz[SK2(0)]; lc[ee] = la[ee]; }
                else        { la[ee] = Zz[SK2(k)]; lc[ee] = Zz[SK2(1024 - k)]; }
                w = cmul(w, WSTEP);
            }
            if (T == 0 && r == 1) z512 = Zz[SK2(512)];
            __syncthreads();
            #pragma unroll
            for (int ee = 0; ee < 4; ee++) {
                int k = T + 64 * (4 * r + ee);
                if (k == 0) {
                    float x0 = la[ee].x + la[ee].y;
                    float x1 = la[ee].x - la[ee].y;
                    Zz[SK2(0)] = make_float2(x0 * x0, x1 * x1);   // (pw0, pw1024)
                } else {
                    float2 a = la[ee], cc = lc[ee], wk = wsv[ee];
                    float ex = 0.5f * (a.x + cc.x);
                    float ey = 0.5f * (a.y - cc.y);
                    float ox = 0.5f * (a.y + cc.y);
                    float oy = -0.5f * (a.x - cc.x);
                    float rw = ox * wk.x - oy * wk.y;
                    float iw = ox * wk.y + oy * wk.x;
                    float xr = ex + rw,  xi = ey + iw;
                    float yr = ex - rw,  yi = -ey + iw;
                    Zz[SK2(k)] = make_float2(xr * xr + xi * xi, yr * yr + yi * yi);
                }
            }
            if (T == 0 && r == 1) {
                float p = z512.x * z512.x + z512.y * z512.y;
                Zz[SK2(512)] = make_float2(p, p);
            }
            __syncthreads();
        }
    }

    // ---- sparse triangular mel projection: thread T does mels T and T+64 ----
    {
        const float df = 16000.0f / 1024.0f;
        #pragma unroll
        for (int h = 0; h < 2; h++) {
            int m = T + 64 * h;
            float f0 = fp[m];
            float f1 = fp[m + 1];
            float f2 = fp[m + 2];
            float inv_d0 = 1.0f / (f1 - f0);
            float inv_d1 = 1.0f / (f2 - f1);
            int klo = max(0, (int)(f0 / df));
            int khi = min(1024, (int)(f2 / df) + 1);
            float acc = 0.0f;
            float freq = (float)klo * df;
            for (int k = klo; k <= khi; k++) {
                float2 s = Zz[SK2(min(k, 1024 - k))];
                float pv = (k <= 512) ? s.x : s.y;
                float wgt = fminf((freq - f0) * inv_d0, (f2 - freq) * inv_d1);
                wgt = fmaxf(wgt, 0.0f);
                acc = fmaf(pv, wgt, acc);
                freq += df;
            }
            g_mel[((size_t)b * NFRM + t) * NMELS + m] = acc;
        }
    }
}

// ---------------- PCEN pass A: per-chunk partial IIR (m0 = 0) ----------------
__global__ __launch_bounds__(128) void pcen_partial_kernel() {
    const int b = blockIdx.x;
    const int c = blockIdx.y;
    const int m = threadIdx.x;
    const int t0 = c * CHLEN;
    const int len = min(CHLEN, NFRM - t0);

    const float* __restrict__ src = g_mel + ((size_t)b * NFRM + t0) * NMELS + m;
    float p = 0.0f;
    for (int k = 0; k < len; k++) {
        float x = src[(size_t)k * NMELS];
        p = fmaf(0.975f, p, 0.025f * x);
    }
    g_part[((size_t)b * NCHUNK + c) * NMELS + m] = p;
}

// ---------------- PCEN pass B: reconstruct state, emit outputs ----------------
__global__ __launch_bounds__(128) void pcen_out_kernel(float* __restrict__ out) {
    __shared__ float sm[NMELS * (CHLEN + 1)];

    const int b = blockIdx.x;
    const int c = blockIdx.y;
    const int m = threadIdx.x;
    const int t0 = c * CHLEN;
    const int len = min(CHLEN, NFRM - t0);

    float pow40 = 1.0f;
    #pragma unroll
    for (int i = 0; i < CHLEN; i++) pow40 *= 0.975f;

    const float* __restrict__ part = g_part + (size_t)b * NCHUNK * NMELS + m;
    float mst = 0.0f;
    for (int cp = 0; cp < c; cp++)
        mst = fmaf(mst, pow40, part[(size_t)cp * NMELS]);

    const float EPS = 1e-6f;
    const float ALPHA = 0.98f;
    const float DELTA = 2.0f;
    const float DELTA_R = 1.41421356237309515f;

    const float* __restrict__ src = g_mel + ((size_t)b * NFRM + t0) * NMELS + m;
    float* __restrict__ row = sm + (size_t)m * (CHLEN + 1);

    for (int k = 0; k < len; k++) {
        float x = src[(size_t)k * NMELS];
        mst = fmaf(0.975f, mst, 0.025f * x);
        float d = ex2_approx(-ALPHA * lg2_approx(EPS + mst));
        row[k] = sqrt_approx(fmaf(x, d, DELTA)) - DELTA_R;
    }
    __syncthreads();

    float* __restrict__ dst = out + (size_t)b * NMELS * NFRM + t0;
    const int total = NMELS * len;
    for (int j = m; j < total; j += NMELS) {
        int mr = j / len;
        int tt = j - mr * len;
        dst[(size_t)mr * NFRM + tt] = sm[(size_t)mr * (CHLEN + 1) + tt];
    }
}

extern "C" void kernel_launch(void* const* d_in, const int* in_sizes, int n_in,
                              void* d_out, int out_size) {
    const float* wave = (const float*)d_in[0];
    float* out = (float*)d_out;

    melspec_kernel<<<(BATCH * NFRM) / 4, 256>>>(wave);   // 5008 blocks

    dim3 pgrid(BATCH, NCHUNK);
    pcen_partial_kernel<<<pgrid, NMELS>>>();
    pcen_out_kernel<<<pgrid, NMELS>>>(out);
}

// round 7
// speedup vs baseline: 5.1341x; 1.2695x over previous
#include <cuda_runtime.h>
#include <math.h>

#define BATCH 64
#define WLEN  160000
#define NFRM  313          // 1 + 160000/512
#define HOP   512
#define NFFT  2048
#define MHALF 1024         // complex FFT length
#define NMELS 128
#define NPTS  130          // mel breakpoints

#define SK2(i) ((i) + ((i) >> 4))    // float2 skew (applied once per access group)
#define ZLEN2  1092                  // >= SK2(1024)+1 = 1089

#define NCHUNK 8
#define CHLEN  40                    // 7*40 + 33 = 313

__device__ float g_mel[BATCH * NFRM * NMELS];    // mel power, layout [b][t][m]
__device__ float g_part[BATCH * NCHUNK * NMELS]; // per-chunk partial IIR sums

__device__ __forceinline__ float2 cmul(float2 a, float2 b) {
    return make_float2(a.x * b.x - a.y * b.y, a.x * b.y + a.y * b.x);
}
__device__ __forceinline__ float sqrt_approx(float x) {
    float r; asm("sqrt.approx.f32 %0, %1;" : "=f"(r) : "f"(x)); return r;
}
__device__ __forceinline__ float lg2_approx(float x) {
    float r; asm("lg2.approx.f32 %0, %1;" : "=f"(r) : "f"(x)); return r;
}
__device__ __forceinline__ float ex2_approx(float x) {
    float r; asm("ex2.approx.f32 %0, %1;" : "=f"(r) : "f"(x)); return r;
}

// radix-4 DIT butterfly with twiddles on a1..a3; slot q receives q-th output.
__device__ __forceinline__ void radix4(float2& a0, float2& a1, float2& a2, float2& a3,
                                       float2 w1, float2 w2, float2 w3) {
    float2 b1 = cmul(a1, w1);
    float2 b2 = cmul(a2, w2);
    float2 b3 = cmul(a3, w3);
    float t0r = a0.x + b2.x, t0i = a0.y + b2.y;
    float t1r = a0.x - b2.x, t1i = a0.y - b2.y;
    float t2r = b1.x + b3.x, t2i = b1.y + b3.y;
    float t3r = b1.y - b3.y, t3i = -(b1.x - b3.x);   // -i*(b1-b3)
    a0 = make_float2(t0r + t2r, t0i + t2i);
    a1 = make_float2(t1r + t3r, t1i + t3i);
    a2 = make_float2(t0r - t2r, t0i - t2i);
    a3 = make_float2(t1r - t3r, t1i - t3i);
}
__device__ __forceinline__ void radix4_nt(float2& a0, float2& a1, float2& a2, float2& a3) {
    float t0r = a0.x + a2.x, t0i = a0.y + a2.y;
    float t1r = a0.x - a2.x, t1i = a0.y - a2.y;
    float t2r = a1.x + a3.x, t2i = a1.y + a3.y;
    float t3r = a1.y - a3.y, t3i = -(a1.x - a3.x);
    a0 = make_float2(t0r + t2r, t0i + t2i);
    a1 = make_float2(t1r + t3r, t1i + t3i);
    a2 = make_float2(t0r - t2r, t0i - t2i);
    a3 = make_float2(t1r - t3r, t1i - t3i);
}

// ---------------- fused frame+window+FFT+power+mel ----------------
// 128 threads = 2 frames x 64 threads; 16 complex points per thread.
__global__ __launch_bounds__(128, 6) void melspec_kernel(const float* __restrict__ wave) {
    __shared__ float2 zz[2][ZLEN2];    // 17.5 KB
    __shared__ float  pw[2][1056];     //  8.4 KB (flat power spectrum)
    __shared__ float  fp[NPTS];

    const int tid = threadIdx.x;
    const int f   = tid >> 6;          // frame within block
    const int T   = tid & 63;          // thread within frame
    const int g   = blockIdx.x * 2 + f;
    const int b   = g / NFRM;
    const int t   = g - b * NFRM;

    float2* __restrict__ Zz = zz[f];
    float*  __restrict__ Pw = pw[f];

    const int skT = T + (T >> 4);      // SK2(T)

    // mel breakpoints (consumed at the end; ordered by later syncs)
    if (tid < 65) {
        const float mlo = 2595.0f * log10f(1.0f + 20.0f / 700.0f);
        const float mhi = 2595.0f * log10f(1.0f + 16000.0f / 700.0f);
        const float dm  = (mhi - mlo) / (float)(NPTS - 1);
        float m0 = mlo + dm * (float)tid;
        fp[tid]      = 700.0f * (exp10f(m0 / 2595.0f) - 1.0f);
        fp[tid + 65] = 700.0f * (exp10f((m0 + 65.0f * dm) / 2595.0f) - 1.0f);
    }

    // ---- staging: frame (reflect pad) * Hann; window via rotor recurrence ----
    const float* __restrict__ wb = wave + (size_t)b * WLEN;
    const int p0 = t * HOP - (NFFT / 2);
    const float CW = (float)M_PI / 1024.0f;     // angle per real sample
    float rs, rc;
    __sincosf(CW * (float)(2 * T), &rs, &rc);
    float2 rot = make_float2(rc, rs);
    const float2 RSTEP = make_float2(0.9238795325112867f, 0.3826834323650898f);   // exp(+i pi/8)
    const float CCW = 0.9999952938095760f;     // cos(pi/1024)
    const float SCW = 0.0030679567629659760f;  // sin(pi/1024)

    if (p0 >= 0 && p0 + NFFT <= WLEN) {
        const float2* __restrict__ wv = (const float2*)(wb + p0) + T;
        #pragma unroll
        for (int e = 0; e < 16; e++) {
            float2 v = wv[64 * e];
            float c1 = rot.x * CCW - rot.y * SCW;
            float w0 = 0.5f - 0.5f * rot.x;
            float w1 = 0.5f - 0.5f * c1;
            Zz[skT + 68 * e] = make_float2(v.x * w0, v.y * w1);
            rot = cmul(rot, RSTEP);
        }
    } else {
        #pragma unroll
        for (int e = 0; e < 16; e++) {
            int n = T + 64 * e;
            int j0 = p0 + 2 * n;
            int j1 = j0 + 1;
            int r0 = (j0 < 0) ? -j0 : ((j0 >= WLEN) ? 2 * WLEN - 2 - j0 : j0);
            int r1 = (j1 < 0) ? -j1 : ((j1 >= WLEN) ? 2 * WLEN - 2 - j1 : j1);
            float c1 = rot.x * CCW - rot.y * SCW;
            float w0 = 0.5f - 0.5f * rot.x;
            float w1 = 0.5f - 0.5f * c1;
            Zz[skT + 68 * e] = make_float2(wb[r0] * w0, wb[r1] * w1);
            rot = cmul(rot, RSTEP);
        }
    }
    __syncthreads();

    // ---- merged stages 0+1: outputs [16T, 16T+16) ----
    {
        float2 y[4][4];   // y[j][p]
        #pragma unroll
        for (int j = 0; j < 4; j++) {
            unsigned old = (unsigned)(4 * T + j);
            unsigned rj = __brev(old) >> 24;
            rj = ((rj & 0x55u) << 1) | ((rj >> 1) & 0x55u);   // base-4 digit reverse
            int skrj = (int)rj + ((int)rj >> 4);
            float2 a0 = Zz[skrj];
            float2 a1 = Zz[skrj + 272];
            float2 a2 = Zz[skrj + 544];
            float2 a3 = Zz[skrj + 816];
            radix4_nt(a0, a1, a2, a3);
            y[j][0] = a0; y[j][1] = a1; y[j][2] = a2; y[j][3] = a3;
        }
        __syncthreads();   // all gathers complete block-wide before any store

        const float2 W16_1[4] = { {1.f,0.f}, {0.92387953251f,-0.38268343236f},
                                  {0.70710678119f,-0.70710678119f}, {0.38268343236f,-0.92387953251f} };
        const float2 W16_2[4] = { {1.f,0.f}, {0.70710678119f,-0.70710678119f},
                                  {0.f,-1.f}, {-0.70710678119f,-0.70710678119f} };
        const float2 W16_3[4] = { {1.f,0.f}, {0.38268343236f,-0.92387953251f},
                                  {-0.70710678119f,-0.70710678119f}, {-0.92387953251f,0.38268343236f} };
        #pragma unroll
        for (int p = 0; p < 4; p++)
            radix4(y[0][p], y[1][p], y[2][p], y[3][p], W16_1[p], W16_2[p], W16_3[p]);

        const int st = 17 * T;   // SK2(16T + c) = 17T + c for c < 16
        #pragma unroll
        for (int q = 0; q < 4; q++)
            #pragma unroll
            for (int p = 0; p < 4; p++)
                Zz[st + p + 4 * q] = y[q][p];
    }
    __syncthreads();

    // ---- merged stages 2+3: thread owns {256C + 16u + j0}, in place ----
    {
        const int C  = T >> 4;
        const int j0 = T & 15;
        const int base = 272 * C + j0;   // SK2(256C + j0); +17u per step
        float2 v[16];
        #pragma unroll
        for (int u = 0; u < 16; u++)
            v[u] = Zz[base + 17 * u];

        // stage 2: twiddle exp(-2*pi*i*j0/64)
        {
            float s, c;
            __sincosf(-(float)M_PI * (float)j0 / 32.0f, &s, &c);
            float2 w1 = make_float2(c, s);
            float2 w2 = cmul(w1, w1);
            float2 w3 = cmul(w2, w1);
            #pragma unroll
            for (int a = 0; a < 4; a++)
                radix4(v[4*a+0], v[4*a+1], v[4*a+2], v[4*a+3], w1, w2, w3);
        }
        // stage 3: w1(bq) = exp(-2*pi*i*(16bq + j0)/256) via rotor
        {
            float s, c;
            __sincosf(-(float)M_PI * (float)j0 / 128.0f, &s, &c);
            float2 w = make_float2(c, s);
            const float2 STEP3 = make_float2(0.9238795325112867f, -0.3826834323650898f); // exp(-i pi/8)
            #pragma unroll
            for (int bq = 0; bq < 4; bq++) {
                float2 w2 = cmul(w, w);
                float2 w3 = cmul(w2, w);
                radix4(v[bq], v[4+bq], v[8+bq], v[12+bq], w, w2, w3);
                w = cmul(w, STEP3);
            }
        }
        #pragma unroll
        for (int u = 0; u < 16; u++)
            Zz[base + 17 * u] = v[u];
    }
    __syncthreads();

    // ---- stage 4: thread owns {4T+d + 256q}, in place; twiddle rotor ----
    {
        float s, c;
        __sincosf(-(float)M_PI * (float)T / 128.0f, &s, &c);     // exp(-2pi*i*4T/1024)
        float2 w = make_float2(c, s);
        const float2 STEP4 = make_float2(0.9999811752826011f, -0.0061358846491544753f); // exp(-2pi i/1024)
        const int sk4 = 4 * T + (T >> 2);    // SK2(4T); +d, +272q
        #pragma unroll
        for (int d = 0; d < 4; d++) {
            float2 a0 = Zz[sk4 + d];
            float2 a1 = Zz[sk4 + d + 272];
            float2 a2 = Zz[sk4 + d + 544];
            float2 a3 = Zz[sk4 + d + 816];
            float2 w2 = cmul(w, w);
            float2 w3 = cmul(w2, w);
            radix4(a0, a1, a2, a3, w, w2, w3);
            Zz[sk4 + d]       = a0;
            Zz[sk4 + d + 272] = a1;
            Zz[sk4 + d + 544] = a2;
            Zz[sk4 + d + 816] = a3;
            w = cmul(w, STEP4);
        }
    }
    __syncthreads();

    // ---- real-FFT unpack -> flat power spectrum pw[0..1024] ----
    // thread T covers k = T + 64e, e = 0..7; each k also yields pw[1024-k].
    {
        float ws, wc;
        __sincosf(-(float)M_PI * (float)T / 1024.0f, &ws, &wc);
        float2 w = make_float2(wc, ws);
        const float2 WSTEP = make_float2(0.9807852804032304f, -0.19509032201612825f);  // exp(-i pi/16)
        const int skc = (1024 - T) + ((1024 - T) >> 4);   // SK2(1024-T); -68e per step

        #pragma unroll
        for (int e = 0; e < 8; e++) {
            int k = T + 64 * e;
            float2 a = Zz[skT + 68 * e];
            if (k == 0) {
                float x0 = a.x + a.y;
                float x1 = a.x - a.y;
                Pw[0]    = x0 * x0;
                Pw[1024] = x1 * x1;
            } else {
                float2 cc = Zz[skc - 68 * e];
                float ex = 0.5f * (a.x + cc.x);
                float ey = 0.5f * (a.y - cc.y);
                float ox = 0.5f * (a.y + cc.y);
                float oy = -0.5f * (a.x - cc.x);
                float rw = ox * w.x - oy * w.y;
                float iw = ox * w.y + oy * w.x;
                float xr = ex + rw,  xi = ey + iw;
                float yr = ex - rw,  yi = -ey + iw;
                Pw[k]        = xr * xr + xi * xi;
                Pw[1024 - k] = yr * yr + yi * yi;
            }
            w = cmul(w, WSTEP);
        }
        if (T == 0) {
            float2 z = Zz[SK2(512)];
            Pw[512] = z.x * z.x + z.y * z.y;
        }
    }
    __syncthreads();

    // ---- sparse triangular mel projection: thread T does mels T and 127-T ----
    {
        const float df = 16000.0f / 1024.0f;
        #pragma unroll
        for (int h = 0; h < 2; h++) {
            int m = h ? (127 - T) : T;
            float f0 = fp[m];
            float f1 = fp[m + 1];
            float f2 = fp[m + 2];
            float inv_d0 = 1.0f / (f1 - f0);
            float inv_d1 = 1.0f / (f2 - f1);
            int klo = max(0, (int)(f0 / df));
            int khi = min(1024, (int)(f2 / df) + 1);
            float acc = 0.0f;
            float freq = (float)klo * df;
            for (int k = klo; k <= khi; k++) {
                float wgt = fminf((freq - f0) * inv_d0, (f2 - freq) * inv_d1);
                wgt = fmaxf(wgt, 0.0f);
                acc = fmaf(Pw[k], wgt, acc);
                freq += df;
            }
            g_mel[((size_t)b * NFRM + t) * NMELS + m] = acc;
        }
    }
}

// ---------------- PCEN pass A: per-chunk partial IIR (m0 = 0) ----------------
__global__ __launch_bounds__(128) void pcen_partial_kernel() {
    const int b = blockIdx.x;
    const int c = blockIdx.y;
    const int m = threadIdx.x;
    const int t0 = c * CHLEN;
    const int len = min(CHLEN, NFRM - t0);

    const float* __restrict__ src = g_mel + ((size_t)b * NFRM + t0) * NMELS + m;
    float p = 0.0f;
    for (int k = 0; k < len; k++) {
        float x = src[(size_t)k * NMELS];
        p = fmaf(0.975f, p, 0.025f * x);
    }
    g_part[((size_t)b * NCHUNK + c) * NMELS + m] = p;
}

// ---------------- PCEN pass B: reconstruct state, emit outputs ----------------
__global__ __launch_bounds__(128) void pcen_out_kernel(float* __restrict__ out) {
    __shared__ float sm[NMELS * (CHLEN + 1)];

    const int b = blockIdx.x;
    const int c = blockIdx.y;
    const int m = threadIdx.x;
    const int t0 = c * CHLEN;
    const int len = min(CHLEN, NFRM - t0);

    float pow40 = 1.0f;
    #pragma unroll
    for (int i = 0; i < CHLEN; i++) pow40 *= 0.975f;

    const float* __restrict__ part = g_part + (size_t)b * NCHUNK * NMELS + m;
    float mst = 0.0f;
    for (int cp = 0; cp < c; cp++)
        mst = fmaf(mst, pow40, part[(size_t)cp * NMELS]);

    const float EPS = 1e-6f;
    const float ALPHA = 0.98f;
    const float DELTA = 2.0f;
    const float DELTA_R = 1.41421356237309515f;

    const float* __restrict__ src = g_mel + ((size_t)b * NFRM + t0) * NMELS + m;
    float* __restrict__ row = sm + (size_t)m * (CHLEN + 1);

    for (int k = 0; k < len; k++) {
        float x = src[(size_t)k * NMELS];
        mst = fmaf(0.975f, mst, 0.025f * x);
        float d = ex2_approx(-ALPHA * lg2_approx(EPS + mst));
        row[k] = sqrt_approx(fmaf(x, d, DELTA)) - DELTA_R;
    }
    __syncthreads();

    float* __restrict__ dst = out + (size_t)b * NMELS * NFRM + t0;
    const int total = NMELS * len;
    for (int j = m; j < total; j += NMELS) {
        int mr = j / len;
        int tt = j - mr * len;
        dst[(size_t)mr * NFRM + tt] = sm[(size_t)mr * (CHLEN + 1) + tt];
    }
}

extern "C" void kernel_launch(void* const* d_in, const int* in_sizes, int n_in,
                              void* d_out, int out_size) {
    const float* wave = (const float*)d_in[0];
    float* out = (float*)d_out;

    melspec_kernel<<<(BATCH * NFRM) / 2, 128>>>(wave);   // 10016 blocks

    dim3 pgrid(BATCH, NCHUNK);
    pcen_partial_kernel<<<pgrid, NMELS>>>();
    pcen_out_kernel<<<pgrid, NMELS>>>(out);
}

// round 8
// speedup vs baseline: 5.9619x; 1.1612x over previous
#include <cuda_runtime.h>
#include <math.h>

#define BATCH 64
#define WLEN  160000
#define NFRM  313          // 1 + 160000/512
#define HOP   512
#define NFFT  2048
#define MHALF 1024         // complex FFT length
#define NMELS 128
#define NPTS  130          // mel breakpoints

#define SK2(i) ((i) + ((i) >> 4))    // skew (slots are float4 now)
#define ZLEN4  1092

#define NCHUNK 8
#define CHLEN  40                    // 7*40 + 33 = 313

typedef unsigned long long ull;

__device__ float g_mel[BATCH * NFRM * NMELS];    // mel power, layout [b][t][m]
__device__ float g_part[BATCH * NCHUNK * NMELS]; // per-chunk partial IIR sums

// ---------------- packed f32x2 helpers ----------------
__device__ __forceinline__ ull pk2(float lo, float hi) {
    ull r; asm("mov.b64 %0, {%1, %2};" : "=l"(r) : "f"(lo), "f"(hi)); return r;
}
__device__ __forceinline__ ull bc2(float v) { return pk2(v, v); }
__device__ __forceinline__ void upk2(float& lo, float& hi, ull v) {
    asm("mov.b64 {%0, %1}, %2;" : "=f"(lo), "=f"(hi) : "l"(v));
}
__device__ __forceinline__ ull add2(ull a, ull b) {
    ull r; asm("add.rn.f32x2 %0, %1, %2;" : "=l"(r) : "l"(a), "l"(b)); return r;
}
__device__ __forceinline__ ull sub2(ull a, ull b) {
    ull r; asm("sub.rn.f32x2 %0, %1, %2;" : "=l"(r) : "l"(a), "l"(b)); return r;
}
__device__ __forceinline__ ull mul2(ull a, ull b) {
    ull r; asm("mul.rn.f32x2 %0, %1, %2;" : "=l"(r) : "l"(a), "l"(b)); return r;
}
__device__ __forceinline__ ull fma2(ull a, ull b, ull c) {
    ull r; asm("fma.rn.f32x2 %0, %1, %2, %3;" : "=l"(r) : "l"(a), "l"(b), "l"(c)); return r;
}

struct c2  { ull re, im; };                 // complex, 2 frames packed per component
struct tw2 { ull r, i, in; };               // packed twiddle: (w.x,w.x),(w.y,w.y),(-w.y,-w.y)

__device__ __forceinline__ float2 cmul(float2 a, float2 b) {
    return make_float2(a.x * b.x - a.y * b.y, a.x * b.y + a.y * b.x);
}
__device__ __forceinline__ tw2 mktw(float2 w) {
    tw2 t; t.r = bc2(w.x); t.i = bc2(w.y); t.in = bc2(-w.y); return t;
}
__device__ __forceinline__ c2 cmul2(c2 a, tw2 w) {
    c2 o;
    o.re = fma2(a.re, w.r, mul2(a.im, w.in));
    o.im = fma2(a.re, w.i, mul2(a.im, w.r));
    return o;
}
__device__ __forceinline__ void radix4p(c2& a0, c2& a1, c2& a2, c2& a3,
                                        tw2 w1, tw2 w2, tw2 w3) {
    c2 b1 = cmul2(a1, w1);
    c2 b2 = cmul2(a2, w2);
    c2 b3 = cmul2(a3, w3);
    ull t0r = add2(a0.re, b2.re), t0i = add2(a0.im, b2.im);
    ull t1r = sub2(a0.re, b2.re), t1i = sub2(a0.im, b2.im);
    ull t2r = add2(b1.re, b3.re), t2i = add2(b1.im, b3.im);
    ull t3r = sub2(b1.im, b3.im), t3i = sub2(b3.re, b1.re);   // -i*(b1-b3)
    a0.re = add2(t0r, t2r); a0.im = add2(t0i, t2i);
    a1.re = add2(t1r, t3r); a1.im = add2(t1i, t3i);
    a2.re = sub2(t0r, t2r); a2.im = sub2(t0i, t2i);
    a3.re = sub2(t1r, t3r); a3.im = sub2(t1i, t3i);
}
__device__ __forceinline__ void radix4p_nt(c2& a0, c2& a1, c2& a2, c2& a3) {
    ull t0r = add2(a0.re, a2.re), t0i = add2(a0.im, a2.im);
    ull t1r = sub2(a0.re, a2.re), t1i = sub2(a0.im, a2.im);
    ull t2r = add2(a1.re, a3.re), t2i = add2(a1.im, a3.im);
    ull t3r = sub2(a1.im, a3.im), t3i = sub2(a3.re, a1.re);
    a0.re = add2(t0r, t2r); a0.im = add2(t0i, t2i);
    a1.re = add2(t1r, t3r); a1.im = add2(t1i, t3i);
    a2.re = sub2(t0r, t2r); a2.im = sub2(t0i, t2i);
    a3.re = sub2(t1r, t3r); a3.im = sub2(t1i, t3i);
}
__device__ __forceinline__ c2 ld4(const float4* p) {
    float4 v = *p;
    c2 a; a.re = pk2(v.x, v.y); a.im = pk2(v.z, v.w); return a;
}
__device__ __forceinline__ void st4(float4* p, c2 a) {
    float4 v;
    upk2(v.x, v.y, a.re);
    upk2(v.z, v.w, a.im);
    *p = v;
}

__device__ __forceinline__ float sqrt_approx(float x) {
    float r; asm("sqrt.approx.f32 %0, %1;" : "=f"(r) : "f"(x)); return r;
}
__device__ __forceinline__ float lg2_approx(float x) {
    float r; asm("lg2.approx.f32 %0, %1;" : "=f"(r) : "f"(x)); return r;
}
__device__ __forceinline__ float ex2_approx(float x) {
    float r; asm("ex2.approx.f32 %0, %1;" : "=f"(r) : "f"(x)); return r;
}
__device__ __forceinline__ int reflect_idx(int j) {
    return (j < 0) ? -j : ((j >= WLEN) ? 2 * WLEN - 2 - j : j);
}

// ---------------- fused frame+window+FFT+power+mel, 2 frames SIMD-packed ----------------
// 64 threads per block; one frame PAIR per block; 16 complex points x 2 frames per thread.
__global__ __launch_bounds__(64, 8) void melspec_kernel(const float* __restrict__ wave) {
    __shared__ float4 zz[ZLEN4];       // (reA, reB, imA, imB)  17.5 KB
    __shared__ ull    pw[1056];        // (pwA, pwB) per bin     8.4 KB
    __shared__ float  fp[NPTS];

    const int T  = threadIdx.x;        // 0..63
    const int gA = blockIdx.x * 2;
    const int gB = gA + 1;
    const int bA = gA / NFRM, tA = gA - bA * NFRM;
    const int bB = gB / NFRM, tB = gB - bB * NFRM;

    const int skT = T + (T >> 4);      // SK2(T)

    // mel breakpoints
    for (int i = T; i < NPTS; i += 64) {
        const float mlo = 2595.0f * log10f(1.0f + 20.0f / 700.0f);
        const float mhi = 2595.0f * log10f(1.0f + 16000.0f / 700.0f);
        float m = mlo + (mhi - mlo) * (float)i / (float)(NPTS - 1);
        fp[i] = 700.0f * (exp10f(m / 2595.0f) - 1.0f);
    }

    // ---- staging: frames (reflect pad) * Hann; window rotor shared by both lanes ----
    const float* __restrict__ wbA = wave + (size_t)bA * WLEN;
    const float* __restrict__ wbB = wave + (size_t)bB * WLEN;
    const int p0A = tA * HOP - (NFFT / 2);
    const int p0B = tB * HOP - (NFFT / 2);
    const float CW = (float)M_PI / 1024.0f;
    float rs, rc;
    __sincosf(CW * (float)(2 * T), &rs, &rc);
    float2 rot = make_float2(rc, rs);
    const float2 RSTEP = make_float2(0.9238795325112867f, 0.3826834323650898f);   // exp(+i pi/8)
    const float CCW = 0.9999952938095760f;     // cos(pi/1024)
    const float SCW = 0.0030679567629659760f;  // sin(pi/1024)

    if (p0A >= 0 && p0B + NFFT <= WLEN && bA == bB) {
        const float2* __restrict__ wvA = (const float2*)(wbA + p0A) + T;
        const float2* __restrict__ wvB = (const float2*)(wbB + p0B) + T;
        #pragma unroll
        for (int e = 0; e < 16; e++) {
            float2 vA = wvA[64 * e];
            float2 vB = wvB[64 * e];
            float c1 = rot.x * CCW - rot.y * SCW;
            float w0 = 0.5f - 0.5f * rot.x;
            float w1 = 0.5f - 0.5f * c1;
            c2 z; z.re = pk2(vA.x * w0, vB.x * w0); z.im = pk2(vA.y * w1, vB.y * w1);
            st4(&zz[skT + 68 * e], z);
            rot = cmul(rot, RSTEP);
        }
    } else {
        #pragma unroll
        for (int e = 0; e < 16; e++) {
            int n = T + 64 * e;
            int jA = p0A + 2 * n, jB = p0B + 2 * n;
            float vAx = wbA[reflect_idx(jA)],     vBx = wbB[reflect_idx(jB)];
            float vAy = wbA[reflect_idx(jA + 1)], vBy = wbB[reflect_idx(jB + 1)];
            float c1 = rot.x * CCW - rot.y * SCW;
            float w0 = 0.5f - 0.5f * rot.x;
            float w1 = 0.5f - 0.5f * c1;
            c2 z; z.re = pk2(vAx * w0, vBx * w0); z.im = pk2(vAy * w1, vBy * w1);
            st4(&zz[skT + 68 * e], z);
            rot = cmul(rot, RSTEP);
        }
    }
    __syncthreads();

    // ---- merged stages 0+1: outputs [16T, 16T+16) ----
    {
        c2 y[4][4];   // y[j][p]
        #pragma unroll
        for (int j = 0; j < 4; j++) {
            unsigned old = (unsigned)(4 * T + j);
            unsigned rj = __brev(old) >> 24;
            rj = ((rj & 0x55u) << 1) | ((rj >> 1) & 0x55u);   // base-4 digit reverse
            int skrj = (int)rj + ((int)rj >> 4);
            c2 a0 = ld4(&zz[skrj]);
            c2 a1 = ld4(&zz[skrj + 272]);
            c2 a2 = ld4(&zz[skrj + 544]);
            c2 a3 = ld4(&zz[skrj + 816]);
            radix4p_nt(a0, a1, a2, a3);
            y[j][0] = a0; y[j][1] = a1; y[j][2] = a2; y[j][3] = a3;
        }
        __syncthreads();   // all gathers complete block-wide before any store

        const float2 W16_1[4] = { {1.f,0.f}, {0.92387953251f,-0.38268343236f},
                                  {0.70710678119f,-0.70710678119f}, {0.38268343236f,-0.92387953251f} };
        const float2 W16_2[4] = { {1.f,0.f}, {0.70710678119f,-0.70710678119f},
                                  {0.f,-1.f}, {-0.70710678119f,-0.70710678119f} };
        const float2 W16_3[4] = { {1.f,0.f}, {0.38268343236f,-0.92387953251f},
                                  {-0.70710678119f,-0.70710678119f}, {-0.92387953251f,0.38268343236f} };
        #pragma unroll
        for (int p = 0; p < 4; p++)
            radix4p(y[0][p], y[1][p], y[2][p], y[3][p],
                    mktw(W16_1[p]), mktw(W16_2[p]), mktw(W16_3[p]));

        const int st = 17 * T;   // SK2(16T + c) = 17T + c, c < 16
        #pragma unroll
        for (int q = 0; q < 4; q++)
            #pragma unroll
            for (int p = 0; p < 4; p++)
                st4(&zz[st + p + 4 * q], y[q][p]);
    }
    __syncthreads();

    // ---- merged stages 2+3: thread owns {256C + 16u + j0}, in place ----
    {
        const int C  = T >> 4;
        const int j0 = T & 15;
        const int base = 272 * C + j0;   // SK2(256C + j0); +17 per u
        c2 v[16];
        #pragma unroll
        for (int u = 0; u < 16; u++)
            v[u] = ld4(&zz[base + 17 * u]);

        // stage 2: twiddle exp(-2*pi*i*j0/64)
        {
            float s, c;
            __sincosf(-(float)M_PI * (float)j0 / 32.0f, &s, &c);
            float2 w1 = make_float2(c, s);
            float2 w2 = cmul(w1, w1);
            float2 w3 = cmul(w2, w1);
            tw2 t1 = mktw(w1), t2 = mktw(w2), t3 = mktw(w3);
            #pragma unroll
            for (int a = 0; a < 4; a++)
                radix4p(v[4*a+0], v[4*a+1], v[4*a+2], v[4*a+3], t1, t2, t3);
        }
        // stage 3: w1(bq) = exp(-2*pi*i*(16bq + j0)/256) via rotor
        {
            float s, c;
            __sincosf(-(float)M_PI * (float)j0 / 128.0f, &s, &c);
            float2 w = make_float2(c, s);
            const float2 STEP3 = make_float2(0.9238795325112867f, -0.3826834323650898f); // exp(-i pi/8)
            #pragma unroll
            for (int bq = 0; bq < 4; bq++) {
                float2 w2 = cmul(w, w);
                float2 w3 = cmul(w2, w);
                radix4p(v[bq], v[4+bq], v[8+bq], v[12+bq], mktw(w), mktw(w2), mktw(w3));
                w = cmul(w, STEP3);
            }
        }
        #pragma unroll
        for (int u = 0; u < 16; u++)
            st4(&zz[base + 17 * u], v[u]);
    }
    __syncthreads();

    // ---- stage 4: thread owns pos = T + 64d (d=0..3), slots skT + 68d + 272q ----
    {
        float s, c;
        __sincosf(-(float)M_PI * (float)T / 512.0f, &s, &c);   // exp(-2pi*i*T/1024)
        float2 w = make_float2(c, s);
        const float2 STEP4 = make_float2(0.9238795325112867f, -0.3826834323650898f);    // exp(-2pi*i*64/1024)
        #pragma unroll
        for (int d = 0; d < 4; d++) {
            const int base = skT + 68 * d;
            c2 a0 = ld4(&zz[base]);
            c2 a1 = ld4(&zz[base + 272]);
            c2 a2 = ld4(&zz[base + 544]);
            c2 a3 = ld4(&zz[base + 816]);
            float2 w2 = cmul(w, w);
            float2 w3 = cmul(w2, w);
            radix4p(a0, a1, a2, a3, mktw(w), mktw(w2), mktw(w3));
            st4(&zz[base],       a0);
            st4(&zz[base + 272], a1);
            st4(&zz[base + 544], a2);
            st4(&zz[base + 816], a3);
            w = cmul(w, STEP4);
        }
    }
    __syncthreads();

    // ---- real-FFT unpack -> packed power pw[k] = (pwA, pwB), k = 0..1024 ----
    {
        float ws, wc;
        __sincosf(-(float)M_PI * (float)T / 1024.0f, &ws, &wc);
        float2 w = make_float2(wc, ws);
        const float2 WSTEP = make_float2(0.9807852804032304f, -0.19509032201612825f);  // exp(-i pi/16)
        const int skc = (1024 - T) + ((1024 - T) >> 4);   // SK2(1024-T); -68 per e
        const ull QUARTER = bc2(0.25f);

        #pragma unroll
        for (int e = 0; e < 8; e++) {
            int k = T + 64 * e;
            c2 a = ld4(&zz[skT + 68 * e]);
            if (k == 0) {
                ull x0 = add2(a.re, a.im);
                ull x1 = sub2(a.re, a.im);
                pw[0]    = mul2(x0, x0);
                pw[1024] = mul2(x1, x1);
            } else {
                c2 cc = ld4(&zz[skc - 68 * e]);
                ull EX = add2(a.re, cc.re);
                ull EY = sub2(a.im, cc.im);
                ull OX = add2(a.im, cc.im);
                ull OY = sub2(cc.re, a.re);
                ull wx = bc2(w.x), wy = bc2(w.y);
                ull RW = sub2(mul2(OX, wx), mul2(OY, wy));
                ull IW = fma2(OX, wy, mul2(OY, wx));
                ull Xr = add2(EX, RW), Xi = add2(EY, IW);
                ull Yr = sub2(EX, RW), Yi = sub2(IW, EY);
                pw[k]        = mul2(fma2(Xi, Xi, mul2(Xr, Xr)), QUARTER);
                pw[1024 - k] = mul2(fma2(Yi, Yi, mul2(Yr, Yr)), QUARTER);
            }
            w = cmul(w, WSTEP);
        }
        if (T == 0) {
            c2 z = ld4(&zz[SK2(512)]);
            pw[512] = fma2(z.im, z.im, mul2(z.re, z.re));
        }
    }
    __syncthreads();

    // ---- mel projection: thread T does mels T and 127-T, both frames packed ----
    {
        const float df = 16000.0f / 1024.0f;
        #pragma unroll
        for (int h = 0; h < 2; h++) {
            int m = h ? (127 - T) : T;
            float f0 = fp[m];
            float f1 = fp[m + 1];
            float f2 = fp[m + 2];
            float inv_d0 = 1.0f / (f1 - f0);
            float inv_d1 = 1.0f / (f2 - f1);
            int klo = max(0, (int)(f0 / df));
            int khi = min(1024, (int)(f2 / df) + 1);
            ull acc = bc2(0.0f);
            float freq = (float)klo * df;
            for (int k = klo; k <= khi; k++) {
                float wgt = fminf((freq - f0) * inv_d0, (f2 - freq) * inv_d1);
                wgt = fmaxf(wgt, 0.0f);
                acc = fma2(pw[k], bc2(wgt), acc);
                freq += df;
            }
            float aA, aB;
            upk2(aA, aB, acc);
            g_mel[((size_t)bA * NFRM + tA) * NMELS + m] = aA;
            g_mel[((size_t)bB * NFRM + tB) * NMELS + m] = aB;
        }
    }
}

// ---------------- PCEN pass A: per-chunk partial IIR (m0 = 0) ----------------
__global__ __launch_bounds__(128) void pcen_partial_kernel() {
    const int b = blockIdx.x;
    const int c = blockIdx.y;
    const int m = threadIdx.x;
    const int t0 = c * CHLEN;
    const int len = min(CHLEN, NFRM - t0);

    const float* __restrict__ src = g_mel + ((size_t)b * NFRM + t0) * NMELS + m;
    float p = 0.0f;
    for (int k = 0; k < len; k++) {
        float x = src[(size_t)k * NMELS];
        p = fmaf(0.975f, p, 0.025f * x);
    }
    g_part[((size_t)b * NCHUNK + c) * NMELS + m] = p;
}

// ---------------- PCEN pass B: reconstruct state, emit outputs ----------------
__global__ __launch_bounds__(128) void pcen_out_kernel(float* __restrict__ out) {
    __shared__ float sm[NMELS * (CHLEN + 1)];

    const int b = blockIdx.x;
    const int c = blockIdx.y;
    const int m = threadIdx.x;
    const int t0 = c * CHLEN;
    const int len = min(CHLEN, NFRM - t0);

    float pow40 = 1.0f;
    #pragma unroll
    for (int i = 0; i < CHLEN; i++) pow40 *= 0.975f;

    const float* __restrict__ part = g_part + (size_t)b * NCHUNK * NMELS + m;
    float mst = 0.0f;
    for (int cp = 0; cp < c; cp++)
        mst = fmaf(mst, pow40, part[(size_t)cp * NMELS]);

    const float EPS = 1e-6f;
    const float ALPHA = 0.98f;
    const float DELTA = 2.0f;
    const float DELTA_R = 1.41421356237309515f;

    const float* __restrict__ src = g_mel + ((size_t)b * NFRM + t0) * NMELS + m;
    float* __restrict__ row = sm + (size_t)m * (CHLEN + 1);

    for (int k = 0; k < len; k++) {
        float x = src[(size_t)k * NMELS];
        mst = fmaf(0.975f, mst, 0.025f * x);
        float d = ex2_approx(-ALPHA * lg2_approx(EPS + mst));
        row[k] = sqrt_approx(fmaf(x, d, DELTA)) - DELTA_R;
    }
    __syncthreads();

    float* __restrict__ dst = out + (size_t)b * NMELS * NFRM + t0;
    const int total = NMELS * len;
    for (int j = m; j < total; j += NMELS) {
        int mr = j / len;
        int tt = j - mr * len;
        dst[(size_t)mr * NFRM + tt] = sm[(size_t)mr * (CHLEN + 1) + tt];
    }
}

extern "C" void kernel_launch(void* const* d_in, const int* in_sizes, int n_in,
                              void* d_out, int out_size) {
    const float* wave = (const float*)d_in[0];
    float* out = (float*)d_out;

    melspec_kernel<<<(BATCH * NFRM) / 2, 64>>>(wave);   // 10016 blocks, 1 frame-pair each

    dim3 pgrid(BATCH, NCHUNK);
    pcen_partial_kernel<<<pgrid, NMELS>>>();
    pcen_out_kernel<<<pgrid, NMELS>>>(out);
}

// round 10
// speedup vs baseline: 6.2996x; 1.0567x over previous
#include <cuda_runtime.h>
#include <math.h>

#define BATCH 64
#define WLEN  160000
#define NFRM  313          // 1 + 160000/512
#define HOP   512
#define NFFT  2048
#define MHALF 1024         // complex FFT length
#define NMELS 128
#define NPTS  130          // mel breakpoints

#define SK2(i) ((i) + ((i) >> 4))    // skew (slots are float4)
#define ZLEN4  1092

#define NCHUNK 8
#define CHLEN  40                    // 7*40 + 33 = 313

typedef unsigned long long ull;

__device__ float g_mel[BATCH * NFRM * NMELS];    // mel power, layout [b][t][m]
__device__ float g_part[BATCH * NCHUNK * NMELS]; // per-chunk partial IIR sums

// ---------------- packed f32x2 helpers ----------------
__device__ __forceinline__ ull pk2(float lo, float hi) {
    ull r; asm("mov.b64 %0, {%1, %2};" : "=l"(r) : "f"(lo), "f"(hi)); return r;
}
__device__ __forceinline__ ull bc2(float v) { return pk2(v, v); }
__device__ __forceinline__ void upk2(float& lo, float& hi, ull v) {
    asm("mov.b64 {%0, %1}, %2;" : "=f"(lo), "=f"(hi) : "l"(v));
}
__device__ __forceinline__ ull add2(ull a, ull b) {
    ull r; asm("add.rn.f32x2 %0, %1, %2;" : "=l"(r) : "l"(a), "l"(b)); return r;
}
__device__ __forceinline__ ull sub2(ull a, ull b) {
    ull r; asm("sub.rn.f32x2 %0, %1, %2;" : "=l"(r) : "l"(a), "l"(b)); return r;
}
__device__ __forceinline__ ull mul2(ull a, ull b) {
    ull r; asm("mul.rn.f32x2 %0, %1, %2;" : "=l"(r) : "l"(a), "l"(b)); return r;
}
__device__ __forceinline__ ull fma2(ull a, ull b, ull c) {
    ull r; asm("fma.rn.f32x2 %0, %1, %2, %3;" : "=l"(r) : "l"(a), "l"(b), "l"(c)); return r;
}

struct c2  { ull re, im; };                 // complex, 2 frames packed per component
struct tw2 { ull r, i, in; };               // packed twiddle

__device__ __forceinline__ float2 cmul(float2 a, float2 b) {
    return make_float2(a.x * b.x - a.y * b.y, a.x * b.y + a.y * b.x);
}
__device__ __forceinline__ tw2 mktw(float2 w) {
    tw2 t; t.r = bc2(w.x); t.i = bc2(w.y); t.in = bc2(-w.y); return t;
}
__device__ __forceinline__ c2 cmul2(c2 a, tw2 w) {
    c2 o;
    o.re = fma2(a.re, w.r, mul2(a.im, w.in));
    o.im = fma2(a.re, w.i, mul2(a.im, w.r));
    return o;
}
__device__ __forceinline__ void radix4p(c2& a0, c2& a1, c2& a2, c2& a3,
                                        tw2 w1, tw2 w2, tw2 w3) {
    c2 b1 = cmul2(a1, w1);
    c2 b2 = cmul2(a2, w2);
    c2 b3 = cmul2(a3, w3);
    ull t0r = add2(a0.re, b2.re), t0i = add2(a0.im, b2.im);
    ull t1r = sub2(a0.re, b2.re), t1i = sub2(a0.im, b2.im);
    ull t2r = add2(b1.re, b3.re), t2i = add2(b1.im, b3.im);
    ull t3r = sub2(b1.im, b3.im), t3i = sub2(b3.re, b1.re);   // -i*(b1-b3)
    a0.re = add2(t0r, t2r); a0.im = add2(t0i, t2i);
    a1.re = add2(t1r, t3r); a1.im = add2(t1i, t3i);
    a2.re = sub2(t0r, t2r); a2.im = sub2(t0i, t2i);
    a3.re = sub2(t1r, t3r); a3.im = sub2(t1i, t3i);
}
__device__ __forceinline__ void radix4p_nt(c2& a0, c2& a1, c2& a2, c2& a3) {
    ull t0r = add2(a0.re, a2.re), t0i = add2(a0.im, a2.im);
    ull t1r = sub2(a0.re, a2.re), t1i = sub2(a0.im, a2.im);
    ull t2r = add2(a1.re, a3.re), t2i = add2(a1.im, a3.im);
    ull t3r = sub2(a1.im, a3.im), t3i = sub2(a3.re, a1.re);
    a0.re = add2(t0r, t2r); a0.im = add2(t0i, t2i);
    a1.re = add2(t1r, t3r); a1.im = add2(t1i, t3i);
    a2.re = sub2(t0r, t2r); a2.im = sub2(t0i, t2i);
    a3.re = sub2(t1r, t3r); a3.im = sub2(t1i, t3i);
}
__device__ __forceinline__ c2 ld4(const float4* p) {
    float4 v = *p;
    c2 a; a.re = pk2(v.x, v.y); a.im = pk2(v.z, v.w); return a;
}
__device__ __forceinline__ void st4(float4* p, c2 a) {
    float4 v;
    upk2(v.x, v.y, a.re);
    upk2(v.z, v.w, a.im);
    *p = v;
}

__device__ __forceinline__ float sqrt_approx(float x) {
    float r; asm("sqrt.approx.f32 %0, %1;" : "=f"(r) : "f"(x)); return r;
}
__device__ __forceinline__ float lg2_approx(float x) {
    float r; asm("lg2.approx.f32 %0, %1;" : "=f"(r) : "f"(x)); return r;
}
__device__ __forceinline__ float ex2_approx(float x) {
    float r; asm("ex2.approx.f32 %0, %1;" : "=f"(r) : "f"(x)); return r;
}
__device__ __forceinline__ int reflect_idx(int j) {
    return (j < 0) ? -j : ((j >= WLEN) ? 2 * WLEN - 2 - j : j);
}

// real-FFT unpack for pair (k, 1024-k): a = z[k], cc = z[1024-k], w = exp(-i*pi*k/1024)
__device__ __forceinline__ void unpack_pair(c2 a, c2 cc, float2 w, ull* __restrict__ pw, int k) {
    ull EX = add2(a.re, cc.re);
    ull EY = sub2(a.im, cc.im);
    ull OX = add2(a.im, cc.im);
    ull OY = sub2(cc.re, a.re);
    ull wx = bc2(w.x), wy = bc2(w.y);
    ull RW = sub2(mul2(OX, wx), mul2(OY, wy));
    ull IW = fma2(OX, wy, mul2(OY, wx));
    ull Xr = add2(EX, RW), Xi = add2(EY, IW);
    ull Yr = sub2(EX, RW), Yi = sub2(IW, EY);
    const ull Q = bc2(0.25f);
    pw[k]        = mul2(fma2(Xi, Xi, mul2(Xr, Xr)), Q);
    pw[1024 - k] = mul2(fma2(Yi, Yi, mul2(Yr, Yr)), Q);
}

// stage-4 butterfly p (loads z[p+256q], applies twiddles, leaves outputs in v[q])
__device__ __forceinline__ void s4_bfly(const float4* __restrict__ zz, int p, float2 w, c2 v[4]) {
    const int o = SK2(p);   // SK2(p+256q) = SK2(p) + 272q  (p < 256)
    v[0] = ld4(&zz[o]);
    v[1] = ld4(&zz[o + 272]);
    v[2] = ld4(&zz[o + 544]);
    v[3] = ld4(&zz[o + 816]);
    float2 w2 = cmul(w, w);
    float2 w3 = cmul(w2, w);
    radix4p(v[0], v[1], v[2], v[3], mktw(w), mktw(w2), mktw(w3));
}

// ---------------- fused frame+window+FFT+power+mel, 2 frames SIMD-packed ----------------
// 64 threads per block; one frame PAIR per block; 16 complex points x 2 frames per thread.
__global__ __launch_bounds__(64, 8) void melspec_kernel(const float* __restrict__ wave) {
    __shared__ float4 zz[ZLEN4];       // (reA, reB, imA, imB)  17.5 KB
    __shared__ ull    pw[1056];        // (pwA, pwB) per bin     8.4 KB
    __shared__ float  fp[NPTS];

    const int T  = threadIdx.x;        // 0..63
    const int gA = blockIdx.x * 2;
    const int gB = gA + 1;
    const int bA = gA / NFRM, tA = gA - bA * NFRM;
    const int bB = gB / NFRM, tB = gB - bB * NFRM;

    const int skT = T + (T >> 4);      // SK2(T)

    // mel breakpoints
    for (int i = T; i < NPTS; i += 64) {
        const float mlo = 2595.0f * log10f(1.0f + 20.0f / 700.0f);
        const float mhi = 2595.0f * log10f(1.0f + 16000.0f / 700.0f);
        float m = mlo + (mhi - mlo) * (float)i / (float)(NPTS - 1);
        fp[i] = 700.0f * (exp10f(m / 2595.0f) - 1.0f);
    }

    // ---- staging: frames (reflect pad) * Hann; window rotor shared by both lanes ----
    const float* __restrict__ wbA = wave + (size_t)bA * WLEN;
    const float* __restrict__ wbB = wave + (size_t)bB * WLEN;
    const int p0A = tA * HOP - (NFFT / 2);
    const int p0B = tB * HOP - (NFFT / 2);
    const float CW = (float)M_PI / 1024.0f;
    float rs, rc;
    __sincosf(CW * (float)(2 * T), &rs, &rc);
    float2 rot = make_float2(rc, rs);
    const float2 RSTEP = make_float2(0.9238795325112867f, 0.3826834323650898f);   // exp(+i pi/8)
    const float CCW = 0.9999952938095760f;     // cos(pi/1024)
    const float SCW = 0.0030679567629659760f;  // sin(pi/1024)

    if (p0A >= 0 && p0B + NFFT <= WLEN && bA == bB) {
        const float2* __restrict__ wvA = (const float2*)(wbA + p0A) + T;
        const float2* __restrict__ wvB = (const float2*)(wbB + p0B) + T;
        #pragma unroll
        for (int e = 0; e < 16; e++) {
            float2 vA = wvA[64 * e];
            float2 vB = wvB[64 * e];
            float c1 = rot.x * CCW - rot.y * SCW;
            float w0 = 0.5f - 0.5f * rot.x;
            float w1 = 0.5f - 0.5f * c1;
            c2 z; z.re = pk2(vA.x * w0, vB.x * w0); z.im = pk2(vA.y * w1, vB.y * w1);
            st4(&zz[skT + 68 * e], z);
            rot = cmul(rot, RSTEP);
        }
    } else {
        #pragma unroll
        for (int e = 0; e < 16; e++) {
            int n = T + 64 * e;
            int jA = p0A + 2 * n, jB = p0B + 2 * n;
            float vAx = wbA[reflect_idx(jA)],     vBx = wbB[reflect_idx(jB)];
            float vAy = wbA[reflect_idx(jA + 1)], vBy = wbB[reflect_idx(jB + 1)];
            float c1 = rot.x * CCW - rot.y * SCW;
            float w0 = 0.5f - 0.5f * rot.x;
            float w1 = 0.5f - 0.5f * c1;
            c2 z; z.re = pk2(vAx * w0, vBx * w0); z.im = pk2(vAy * w1, vBy * w1);
            st4(&zz[skT + 68 * e], z);
            rot = cmul(rot, RSTEP);
        }
    }
    __syncthreads();

    // ---- merged stages 0+1: outputs [16T, 16T+16) ----
    {
        c2 y[4][4];   // y[j][p]
        #pragma unroll
        for (int j = 0; j < 4; j++) {
            unsigned old = (unsigned)(4 * T + j);
            unsigned rj = __brev(old) >> 24;
            rj = ((rj & 0x55u) << 1) | ((rj >> 1) & 0x55u);   // base-4 digit reverse
            int skrj = (int)rj + ((int)rj >> 4);
            c2 a0 = ld4(&zz[skrj]);
            c2 a1 = ld4(&zz[skrj + 272]);
            c2 a2 = ld4(&zz[skrj + 544]);
            c2 a3 = ld4(&zz[skrj + 816]);
            radix4p_nt(a0, a1, a2, a3);
            y[j][0] = a0; y[j][1] = a1; y[j][2] = a2; y[j][3] = a3;
        }
        __syncthreads();   // all gathers complete block-wide before any store

        const float2 W16_1[4] = { {1.f,0.f}, {0.92387953251f,-0.38268343236f},
                                  {0.70710678119f,-0.70710678119f}, {0.38268343236f,-0.92387953251f} };
        const float2 W16_2[4] = { {1.f,0.f}, {0.70710678119f,-0.70710678119f},
                                  {0.f,-1.f}, {-0.70710678119f,-0.70710678119f} };
        const float2 W16_3[4] = { {1.f,0.f}, {0.38268343236f,-0.92387953251f},
                                  {-0.70710678119f,-0.70710678119f}, {-0.92387953251f,0.38268343236f} };
        #pragma unroll
        for (int p = 0; p < 4; p++)
            radix4p(y[0][p], y[1][p], y[2][p], y[3][p],
                    mktw(W16_1[p]), mktw(W16_2[p]), mktw(W16_3[p]));

        const int st = 17 * T;   // SK2(16T + c) = 17T + c, c < 16
        #pragma unroll
        for (int q = 0; q < 4; q++)
            #pragma unroll
            for (int p = 0; p < 4; p++)
                st4(&zz[st + p + 4 * q], y[q][p]);
    }
    __syncthreads();

    // ---- merged stages 2+3: thread owns {256C + 16u + j0}, in place ----
    {
        const int C  = T >> 4;
        const int j0 = T & 15;
        const int base = 272 * C + j0;   // SK2(256C + j0); +17 per u
        c2 v[16];
        #pragma unroll
        for (int u = 0; u < 16; u++)
            v[u] = ld4(&zz[base + 17 * u]);

        // stage 2: twiddle exp(-2*pi*i*j0/64)
        {
            float s, c;
            __sincosf(-(float)M_PI * (float)j0 / 32.0f, &s, &c);
            float2 w1 = make_float2(c, s);
            float2 w2 = cmul(w1, w1);
            float2 w3 = cmul(w2, w1);
            tw2 t1 = mktw(w1), t2 = mktw(w2), t3 = mktw(w3);
            #pragma unroll
            for (int a = 0; a < 4; a++)
                radix4p(v[4*a+0], v[4*a+1], v[4*a+2], v[4*a+3], t1, t2, t3);
        }
        // stage 3: w1(bq) = exp(-2*pi*i*(16bq + j0)/256) via rotor
        {
            float s, c;
            __sincosf(-(float)M_PI * (float)j0 / 128.0f, &s, &c);
            float2 w = make_float2(c, s);
            const float2 STEP3 = make_float2(0.9238795325112867f, -0.3826834323650898f); // exp(-i pi/8)
            #pragma unroll
            for (int bq = 0; bq < 4; bq++) {
                float2 w2 = cmul(w, w);
                float2 w3 = cmul(w2, w);
                radix4p(v[bq], v[4+bq], v[8+bq], v[12+bq], mktw(w), mktw(w2), mktw(w3));
                w = cmul(w, STEP3);
            }
        }
        #pragma unroll
        for (int u = 0; u < 16; u++)
            st4(&zz[base + 17 * u], v[u]);
    }
    __syncthreads();

    // ---- stage 4 + real-FFT unpack fused in registers ----
    // thread T owns the pairing-closed butterfly set {T, 256-T, 127-T, 129+T}
    // (T=0: {0, 128, 127, 129}); butterfly p outputs z[p+256q], whose unpack
    // partners 1024-(p+256q) = (256-p)+256(3-q) live in the same thread.
    {
        // stage-4 twiddles: w(p) = exp(-2*pi*i*p/1024)
        float s4, c4;
        __sincosf(-(float)M_PI * (float)T / 512.0f, &s4, &c4);
        float2 wA = make_float2(c4, s4);                       // w(T)
        const float2 c1s = make_float2(0.9999811752826011f, -0.0061358846491544753f); // w(1)
        float2 wT1 = cmul(wA, c1s);                            // w(T+1)
        const float R2 = 0.70710678118654752f;
        const float2 K4 = make_float2(R2, -R2);                // exp(-i pi/4) = w(128) = wh(256)
        float2 wB = (T == 0) ? K4 : make_float2(-wA.y, -wA.x); // w(256-T); T=0 -> w(128)
        float2 wC = cmul(K4, make_float2(wT1.x, -wT1.y));      // w(127-T)
        float2 wD = cmul(K4, wT1);                             // w(129+T)

        // unpack half-twiddles: wh(p) = exp(-i*pi*p/1024)
        float hs, hc;
        __sincosf(-(float)M_PI * (float)T / 1024.0f, &hs, &hc);
        float2 whA = make_float2(hc, hs);                      // wh(T)
        const float2 ch1 = make_float2(0.9999952938095760f, -0.0030679567629659760f); // wh(1)
        float2 whT1 = cmul(whA, ch1);                          // wh(T+1)
        const float2 K8 = make_float2(0.92387953251128674f, -0.38268343236508977f);   // wh(128) = exp(-i pi/8)
        float2 whC = cmul(K8, make_float2(whT1.x, -whT1.y));   // wh(127-T)

        const float2 Cq[4] = { {1.f, 0.f}, {R2, -R2}, {0.f, -1.f}, {-R2, -R2} };  // wh(256q)

        const int pA = T;
        const int pB = (T == 0) ? 128 : 256 - T;
        const int pC = 127 - T;
        const int pD = 129 + T;

        // group 1: butterflies pA, pB
        {
            c2 vA[4], vB[4];
            s4_bfly(zz, pA, wA, vA);
            s4_bfly(zz, pB, wB, vB);
            if (T == 0) {
                // DC / Nyquist from z[0]
                ull x0 = add2(vA[0].re, vA[0].im);
                ull x1 = sub2(vA[0].re, vA[0].im);
                pw[0]    = mul2(x0, x0);
                pw[1024] = mul2(x1, x1);
                unpack_pair(vA[1], vA[3], K4,                     pw, 256);   // wh(256)
                unpack_pair(vA[2], vA[2], make_float2(0.f, -1.f), pw, 512);   // wh(512)
                unpack_pair(vB[0], vB[3], K8,                     pw, 128);   // wh(128)
                unpack_pair(vB[1], vB[2], cmul(K8, Cq[1]),        pw, 384);   // wh(384)
            } else {
                #pragma unroll
                for (int q = 0; q < 4; q++)
                    unpack_pair(vA[q], vB[3 - q], cmul(whA, Cq[q]), pw, pA + 256 * q);
            }
        }
        // group 2: butterflies pC, pD (uniform for all threads)
        {
            c2 vC[4], vD[4];
            s4_bfly(zz, pC, wC, vC);
            s4_bfly(zz, pD, wD, vD);
            #pragma unroll
            for (int q = 0; q < 4; q++)
                unpack_pair(vC[q], vD[3 - q], cmul(whC, Cq[q]), pw, pC + 256 * q);
        }
    }
    __syncthreads();

    // ---- mel projection: thread T does mels T and 127-T, both frames packed ----
    {
        const float df = 16000.0f / 1024.0f;
        #pragma unroll
        for (int h = 0; h < 2; h++) {
            int m = h ? (127 - T) : T;
            float f0 = fp[m];
            float f1 = fp[m + 1];
            float f2 = fp[m + 2];
            float inv_d0 = 1.0f / (f1 - f0);
            float inv_d1 = 1.0f / (f2 - f1);
            int klo = max(0, (int)(f0 / df));
            int khi = min(1024, (int)(f2 / df) + 1);
            ull acc = bc2(0.0f);
            float freq = (float)klo * df;
            for (int k = klo; k <= khi; k++) {
                float wgt = fminf((freq - f0) * inv_d0, (f2 - freq) * inv_d1);
                wgt = fmaxf(wgt, 0.0f);
                acc = fma2(pw[k], bc2(wgt), acc);
                freq += df;
            }
            float aA, aB;
            upk2(aA, aB, acc);
            g_mel[((size_t)bA * NFRM + tA) * NMELS + m] = aA;
            g_mel[((size_t)bB * NFRM + tB) * NMELS + m] = aB;
        }
    }
}

// ---------------- PCEN pass A: per-chunk partial IIR (m0 = 0) ----------------
__global__ __launch_bounds__(128) void pcen_partial_kernel() {
    const int b = blockIdx.x;
    const int c = blockIdx.y;
    const int m = threadIdx.x;
    const int t0 = c * CHLEN;
    const int len = min(CHLEN, NFRM - t0);

    const float* __restrict__ src = g_mel + ((size_t)b * NFRM + t0) * NMELS + m;
    float p = 0.0f;
    for (int k = 0; k < len; k++) {
        float x = src[(size_t)k * NMELS];
        p = fmaf(0.975f, p, 0.025f * x);
    }
    g_part[((size_t)b * NCHUNK + c) * NMELS + m] = p;
}

// ---------------- PCEN pass B: reconstruct state, emit outputs ----------------
__global__ __launch_bounds__(128) void pcen_out_kernel(float* __restrict__ out) {
    __shared__ float sm[NMELS * (CHLEN + 1)];

    const int b = blockIdx.x;
    const int c = blockIdx.y;
    const int m = threadIdx.x;
    const int t0 = c * CHLEN;
    const int len = min(CHLEN, NFRM - t0);

    float pow40 = 1.0f;
    #pragma unroll
    for (int i = 0; i < CHLEN; i++) pow40 *= 0.975f;

    const float* __restrict__ part = g_part + (size_t)b * NCHUNK * NMELS + m;
    float mst = 0.0f;
    for (int cp = 0; cp < c; cp++)
        mst = fmaf(mst, pow40, part[(size_t)cp * NMELS]);

    const float EPS = 1e-6f;
    const float ALPHA = 0.98f;
    const float DELTA = 2.0f;
    const float DELTA_R = 1.41421356237309515f;

    const float* __restrict__ src = g_mel + ((size_t)b * NFRM + t0) * NMELS + m;
    float* __restrict__ row = sm + (size_t)m * (CHLEN + 1);

    for (int k = 0; k < len; k++) {
        float x = src[(size_t)k * NMELS];
        mst = fmaf(0.975f, mst, 0.025f * x);
        float d = ex2_approx(-ALPHA * lg2_approx(EPS + mst));
        row[k] = sqrt_approx(fmaf(x, d, DELTA)) - DELTA_R;
    }
    __syncthreads();

    float* __restrict__ dst = out + (size_t)b * NMELS * NFRM + t0;
    const int total = NMELS * len;
    for (int j = m; j < total; j += NMELS) {
        int mr = j / len;
        int tt = j - mr * len;
        dst[(size_t)mr * NFRM + tt] = sm[(size_t)mr * (CHLEN + 1) + tt];
    }
}

extern "C" void kernel_launch(void* const* d_in, const int* in_sizes, int n_in,
                              void* d_out, int out_size) {
    const float* wave = (const float*)d_in[0];
    float* out = (float*)d_out;

    melspec_kernel<<<(BATCH * NFRM) / 2, 64>>>(wave);   // 10016 blocks, 1 frame-pair each

    dim3 pgrid(BATCH, NCHUNK);
    pcen_partial_kernel<<<pgrid, NMELS>>>();
    pcen_out_kernel<<<pgrid, NMELS>>>(out);
}